// round 1
// baseline (speedup 1.0000x reference)
#include <cuda_runtime.h>
#include <cstdint>

// Problem constants (fixed shapes)
#define BB   2
#define CC   512
#define TT   16
#define HH   32
#define WW   32
#define NH   8          // heads
#define CH   64         // c / heads
#define BSEQ (BB*HH*WW)     // 2048
#define ROWS (BSEQ*TT)      // 32768

// Scratch (device globals; allocated at module load, not by us)
__device__ float g_nrm[(size_t)ROWS * CC];          // layernorm output; reused for proj output
__device__ float g_qkv[(size_t)ROWS * 3 * CC];      // qkv projection output
__device__ float g_att[(size_t)ROWS * CC];          // attention output

// ---------------------------------------------------------------------------
// K1: (b,c,t,h,w) -> LayerNorm over c -> g_nrm[(b*1024+h*32+w)*16 + t][c]
// One block per (b,t,h). Stats via per-thread strided partials (coalesced),
// then chunked smem transpose for coalesced writes.
// ---------------------------------------------------------------------------
__global__ __launch_bounds__(256) void k1_ln(const float* __restrict__ x,
                                             const float* __restrict__ gamma,
                                             const float* __restrict__ beta,
                                             float* __restrict__ nrm) {
    int bid = blockIdx.x;
    int b = bid >> 9;
    int t = (bid >> 5) & 15;
    int h = bid & 31;
    int tid = threadIdx.x;
    int lane = tid & 31, r = tid >> 5;

    // x element (cc, w): base + cc*16384 + w
    size_t base = (size_t)b * (CC * TT * HH * WW) + (size_t)t * (HH * WW) + (size_t)h * WW;

    float s = 0.f, s2 = 0.f;
    for (int cc = r; cc < CC; cc += 8) {
        float v = x[base + (size_t)cc * (TT*HH*WW) + lane];
        s += v; s2 += v * v;
    }
    __shared__ float red0[8][32], red1[8][32];
    __shared__ float mu_s[32], rs_s[32];
    red0[r][lane] = s; red1[r][lane] = s2;
    __syncthreads();
    if (tid < 32) {
        float a = 0.f, q = 0.f;
        #pragma unroll
        for (int i = 0; i < 8; i++) { a += red0[i][tid]; q += red1[i][tid]; }
        float mu = a * (1.f / CC);
        float var = q * (1.f / CC) - mu * mu;
        mu_s[tid] = mu;
        rs_s[tid] = rsqrtf(var + 1e-5f);
    }
    __syncthreads();

    // output row base for w=0: ((b*1024 + h*32)*16 + t)*512 ; +w*8192 per w
    size_t obase = ((size_t)(b * 1024 + h * 32) * TT + t) * CC;

    __shared__ float tile[128 * 33];
    for (int c0 = 0; c0 < CC; c0 += 128) {
        __syncthreads();
        for (int e = tid; e < 128 * 32; e += 256) {
            int cc = e >> 5, w = e & 31;
            tile[cc * 33 + w] = x[base + (size_t)(c0 + cc) * (TT*HH*WW) + w];
        }
        __syncthreads();
        for (int e = tid; e < 128 * 32; e += 256) {
            int w = e >> 7, cc = e & 127;
            float v = (tile[cc * 33 + w] - mu_s[w]) * rs_s[w] * gamma[c0 + cc] + beta[c0 + cc];
            nrm[obase + (size_t)w * (TT * CC) + c0 + cc] = v;
        }
    }
}

// ---------------------------------------------------------------------------
// SGEMM-NT: C[m][n] = sum_k A[m][k] * W[n][k] + bias[n]
// A: M x K row-major, W: N x K row-major. BM=BN=128, BK=16, 8x8 per thread.
// M % 128 == 0, N % 128 == 0, K % 16 == 0 guaranteed by call sites.
// ---------------------------------------------------------------------------
__global__ __launch_bounds__(256) void sgemm_nt(const float* __restrict__ A,
                                                const float* __restrict__ W,
                                                const float* __restrict__ bias,
                                                float* __restrict__ C,
                                                int M, int N, int K) {
    __shared__ float As[16 * 128];
    __shared__ float Bs[16 * 128];
    int bm = blockIdx.y, bn = blockIdx.x;
    int tid = threadIdx.x;
    int tx = tid & 15, ty = tid >> 4;

    const float* Ab = A + (size_t)bm * 128 * K;
    const float* Wb = W + (size_t)bn * 128 * K;

    float acc[8][8];
    #pragma unroll
    for (int i = 0; i < 8; i++)
        #pragma unroll
        for (int j = 0; j < 8; j++) acc[i][j] = 0.f;

    for (int kt = 0; kt < K; kt += 16) {
        #pragma unroll
        for (int l = 0; l < 2; l++) {
            int f = tid + l * 256;           // 0..511
            int row = f >> 2;
            int kq  = (f & 3) << 2;
            float4 va = *(const float4*)(Ab + (size_t)row * K + kt + kq);
            As[(kq + 0) * 128 + row] = va.x;
            As[(kq + 1) * 128 + row] = va.y;
            As[(kq + 2) * 128 + row] = va.z;
            As[(kq + 3) * 128 + row] = va.w;
            float4 vb = *(const float4*)(Wb + (size_t)row * K + kt + kq);
            Bs[(kq + 0) * 128 + row] = vb.x;
            Bs[(kq + 1) * 128 + row] = vb.y;
            Bs[(kq + 2) * 128 + row] = vb.z;
            Bs[(kq + 3) * 128 + row] = vb.w;
        }
        __syncthreads();
        #pragma unroll
        for (int kk = 0; kk < 16; kk++) {
            float a[8], bf[8];
            #pragma unroll
            for (int i = 0; i < 8; i++) a[i]  = As[kk * 128 + ty * 8 + i];
            #pragma unroll
            for (int j = 0; j < 8; j++) bf[j] = Bs[kk * 128 + tx * 8 + j];
            #pragma unroll
            for (int i = 0; i < 8; i++)
                #pragma unroll
                for (int j = 0; j < 8; j++)
                    acc[i][j] = fmaf(a[i], bf[j], acc[i][j]);
        }
        __syncthreads();
    }

    int row0 = bm * 128 + ty * 8;
    int col0 = bn * 128 + tx * 8;
    float bv[8];
    #pragma unroll
    for (int j = 0; j < 8; j++) bv[j] = bias[col0 + j];
    #pragma unroll
    for (int i = 0; i < 8; i++) {
        float4 v0, v1;
        v0.x = acc[i][0] + bv[0]; v0.y = acc[i][1] + bv[1];
        v0.z = acc[i][2] + bv[2]; v0.w = acc[i][3] + bv[3];
        v1.x = acc[i][4] + bv[4]; v1.y = acc[i][5] + bv[5];
        v1.z = acc[i][6] + bv[6]; v1.w = acc[i][7] + bv[7];
        float* cp = C + (size_t)(row0 + i) * N + col0;
        *(float4*)(cp)     = v0;
        *(float4*)(cp + 4) = v1;
    }
}

// ---------------------------------------------------------------------------
// K3: attention per (B-seq, head). t=16, ch=64.
// weight[i][j] = (q_i . (k_j + k_table[j-i+64])) / 8 ; softmax over j
// a[i] = sum_j attn[i][j] * (v_j + v_table[j-i+64])
// ---------------------------------------------------------------------------
__global__ __launch_bounds__(256) void k3_attn(const float* __restrict__ qkv,
                                               const float* __restrict__ k_table,
                                               const float* __restrict__ v_table,
                                               float* __restrict__ aout) {
    int blk = blockIdx.x;
    int Bidx = blk >> 3;
    int hh = blk & 7;
    int tid = threadIdx.x;

    __shared__ float qs[16 * 65], ks[16 * 65], vs[16 * 65];
    __shared__ float ktab[31 * 65], vtab[31 * 65];
    __shared__ float attn[16 * 17];

    size_t rowbase = (size_t)Bidx * TT * (3 * CC) + hh * CH;
    for (int e = tid; e < 16 * 64; e += 256) {
        int i = e >> 6, cc = e & 63;
        size_t off = rowbase + (size_t)i * (3 * CC) + cc;
        qs[i * 65 + cc] = qkv[off];
        ks[i * 65 + cc] = qkv[off + CC];
        vs[i * 65 + cc] = qkv[off + 2 * CC];
    }
    // relative offsets j-i in [-15,15] -> table rows 49..79
    for (int e = tid; e < 31 * 64; e += 256) {
        int rr = e >> 6, cc = e & 63;
        ktab[rr * 65 + cc] = k_table[(49 + rr) * CH + cc];
        vtab[rr * 65 + cc] = v_table[(49 + rr) * CH + cc];
    }
    __syncthreads();

    // scores: one (i,j) per thread
    {
        int i = tid >> 4, j = tid & 15;
        const float* kr = &ktab[(j - i + 15) * 65];
        const float* qr = &qs[i * 65];
        const float* krow = &ks[j * 65];
        float s = 0.f;
        #pragma unroll
        for (int cc = 0; cc < 64; cc++)
            s = fmaf(qr[cc], krow[cc] + kr[cc], s);
        s *= 0.125f;   // scale^2 = 1/sqrt(64)

        float m = s;
        #pragma unroll
        for (int o = 8; o; o >>= 1)
            m = fmaxf(m, __shfl_xor_sync(0xffffffffu, m, o));
        float e1 = expf(s - m);
        float sum = e1;
        #pragma unroll
        for (int o = 8; o; o >>= 1)
            sum += __shfl_xor_sync(0xffffffffu, sum, o);
        attn[i * 17 + j] = e1 / sum;
    }
    __syncthreads();

    // output: 4 channels per thread
    {
        int oi = tid >> 4;
        int cb = (tid & 15) * 4;
        float o0 = 0.f, o1 = 0.f, o2 = 0.f, o3 = 0.f;
        #pragma unroll
        for (int jj = 0; jj < 16; jj++) {
            float aw = attn[oi * 17 + jj];
            const float* vr = &vtab[(jj - oi + 15) * 65 + cb];
            const float* vv = &vs[jj * 65 + cb];
            o0 = fmaf(aw, vv[0] + vr[0], o0);
            o1 = fmaf(aw, vv[1] + vr[1], o1);
            o2 = fmaf(aw, vv[2] + vr[2], o2);
            o3 = fmaf(aw, vv[3] + vr[3], o3);
        }
        float4 ov = make_float4(o0, o1, o2, o3);
        *(float4*)(aout + (size_t)(Bidx * TT + oi) * CC + hh * CH + cb) = ov;
    }
}

// ---------------------------------------------------------------------------
// K5: out[b,c,t,h,w] = x[b,c,t,h,w] + proj_seq[(b*1024+h*32+w)*16+t][c]
// Same block decomposition as K1; smem transpose for coalescing both sides.
// ---------------------------------------------------------------------------
__global__ __launch_bounds__(256) void k5_resid(const float* __restrict__ x,
                                                const float* __restrict__ oseq,
                                                float* __restrict__ out) {
    int bid = blockIdx.x;
    int b = bid >> 9;
    int t = (bid >> 5) & 15;
    int h = bid & 31;
    int tid = threadIdx.x;

    size_t base  = (size_t)b * (CC * TT * HH * WW) + (size_t)t * (HH * WW) + (size_t)h * WW;
    size_t obase = ((size_t)(b * 1024 + h * 32) * TT + t) * CC;

    __shared__ float tile[128 * 33];
    for (int c0 = 0; c0 < CC; c0 += 128) {
        __syncthreads();
        for (int e = tid; e < 128 * 32; e += 256) {
            int w = e >> 7, cc = e & 127;
            tile[cc * 33 + w] = oseq[obase + (size_t)w * (TT * CC) + c0 + cc];
        }
        __syncthreads();
        for (int e = tid; e < 128 * 32; e += 256) {
            int cc = e >> 5, w = e & 31;
            size_t gi = base + (size_t)(c0 + cc) * (TT*HH*WW) + w;
            out[gi] = x[gi] + tile[cc * 33 + w];
        }
    }
}

// ---------------------------------------------------------------------------
extern "C" void kernel_launch(void* const* d_in, const int* in_sizes, int n_in,
                              void* d_out, int out_size) {
    const float* x       = (const float*)d_in[0];
    const float* ln_g    = (const float*)d_in[1];
    const float* ln_b    = (const float*)d_in[2];
    const float* qkv_w   = (const float*)d_in[3];
    const float* qkv_b   = (const float*)d_in[4];
    const float* k_table = (const float*)d_in[5];
    const float* v_table = (const float*)d_in[6];
    const float* proj_w  = (const float*)d_in[7];
    const float* proj_b  = (const float*)d_in[8];
    float* out = (float*)d_out;

    void *p_nrm_v, *p_qkv_v, *p_att_v;
    cudaGetSymbolAddress(&p_nrm_v, g_nrm);
    cudaGetSymbolAddress(&p_qkv_v, g_qkv);
    cudaGetSymbolAddress(&p_att_v, g_att);
    float* p_nrm = (float*)p_nrm_v;
    float* p_qkv = (float*)p_qkv_v;
    float* p_att = (float*)p_att_v;

    // K1: layernorm + layout transform
    k1_ln<<<BB * TT * HH, 256>>>(x, ln_g, ln_b, p_nrm);

    // K2: qkv = nrm @ qkv_w^T + qkv_b   (32768 x 1536 x 512)
    {
        dim3 grid(3 * CC / 128, ROWS / 128);
        sgemm_nt<<<grid, 256>>>(p_nrm, qkv_w, qkv_b, p_qkv, ROWS, 3 * CC, CC);
    }

    // K3: attention per (seq, head)
    k3_attn<<<BSEQ * NH, 256>>>(p_qkv, k_table, v_table, p_att);

    // K4: proj = att @ proj_w^T + proj_b  (32768 x 512 x 512), reuse g_nrm
    {
        dim3 grid(CC / 128, ROWS / 128);
        sgemm_nt<<<grid, 256>>>(p_att, proj_w, proj_b, p_nrm, ROWS, CC, CC);
    }

    // K5: residual add + transform back to (b,c,t,h,w)
    k5_resid<<<BB * TT * HH, 256>>>(x, p_nrm, out);
}

// round 3
// speedup vs baseline: 2.3901x; 2.3901x over previous
#include <cuda_runtime.h>
#include <cstdint>

#define BB   2
#define CC   512
#define TT   16
#define HH   32
#define WW   32
#define NH   8
#define CH   64
#define BSEQ (BB*HH*WW)     // 2048
#define ROWS (BSEQ*TT)      // 32768

__device__ float g_nrm[(size_t)ROWS * CC];
__device__ float g_qkv[(size_t)ROWS * 3 * CC];
__device__ float g_att[(size_t)ROWS * CC];

// ---------------------------------------------------------------------------
__device__ __forceinline__ uint32_t smem_u32(const void* p) {
    uint32_t a;
    asm("{ .reg .u64 t; cvta.to.shared.u64 t, %1; cvt.u32.u64 %0, t; }" : "=r"(a) : "l"(p));
    return a;
}
#define SWZ(o) ((o) ^ ((((uint32_t)(o)) >> 3) & 0x70))

__device__ __forceinline__ void cpasync16(uint32_t dst, const void* src) {
    asm volatile("cp.async.cg.shared.global [%0], [%1], 16;" :: "r"(dst), "l"(src));
}
__device__ __forceinline__ void ldsm_x4(uint32_t* r, uint32_t addr) {
    asm volatile("ldmatrix.sync.aligned.m8n8.x4.shared.b16 {%0,%1,%2,%3}, [%4];"
                 : "=r"(r[0]), "=r"(r[1]), "=r"(r[2]), "=r"(r[3]) : "r"(addr));
}
__device__ __forceinline__ uint32_t f2tf(uint32_t x) {
    uint32_t y;
    asm("cvt.rna.tf32.f32 %0, %1;" : "=r"(y) : "r"(x));
    return y;
}
__device__ __forceinline__ void mma_tf32(float* c, const uint32_t* a, uint32_t b0, uint32_t b1) {
    asm volatile(
        "mma.sync.aligned.m16n8k8.row.col.f32.tf32.tf32.f32 "
        "{%0,%1,%2,%3}, {%4,%5,%6,%7}, {%8,%9}, {%0,%1,%2,%3};"
        : "+f"(c[0]), "+f"(c[1]), "+f"(c[2]), "+f"(c[3])
        : "r"(a[0]), "r"(a[1]), "r"(a[2]), "r"(a[3]), "r"(b0), "r"(b1));
}

// ---------------------------------------------------------------------------
// TF32 tensor GEMM-NT: C[M,N] = A[M,K] @ W[N,K]^T + bias
// CTA 128x128, BK=32, 8 warps each 64(m)x32(n), 3-stage cp.async pipeline.
// ---------------------------------------------------------------------------
#define NSTAGE   3
#define STAGE_SZ 32768               // A 16KB + B 16KB
#define GSMEM_SZ (NSTAGE*STAGE_SZ)

__global__ __launch_bounds__(256, 1) void tc_gemm(const float* __restrict__ A,
                                                  const float* __restrict__ W,
                                                  const float* __restrict__ bias,
                                                  float* __restrict__ C,
                                                  int M, int N, int K) {
    extern __shared__ __align__(1024) char smraw[];
    const uint32_t base = smem_u32(smraw);

    const int tid  = threadIdx.x;
    const int wid  = tid >> 5, lane = tid & 31;
    const int wm   = wid & 1, wn = wid >> 1;       // warp tile: (wm*64, wn*32)
    const int bn   = blockIdx.x, bm = blockIdx.y;
    const int nch  = K >> 5;

    auto load_chunk = [&](int l) {
        const int k0 = l << 5;
        const uint32_t sA = base + (l % NSTAGE) * STAGE_SZ;
        const uint32_t sB = sA + 16384;
        #pragma unroll
        for (int it = 0; it < 4; it++) {
            int idx = tid + it * 256;
            int r = idx >> 3, c16 = idx & 7;
            cpasync16(sA + SWZ(r * 128 + c16 * 16),
                      A + (size_t)(bm * 128 + r) * K + k0 + c16 * 4);
            cpasync16(sB + SWZ(r * 128 + c16 * 16),
                      W + (size_t)(bn * 128 + r) * K + k0 + c16 * 4);
        }
        asm volatile("cp.async.commit_group;" ::: "memory");
    };

    load_chunk(0);
    load_chunk(1);

    float acc[4][4][4];
    #pragma unroll
    for (int f = 0; f < 4; f++)
        #pragma unroll
        for (int g = 0; g < 4; g++)
            #pragma unroll
            for (int r = 0; r < 4; r++) acc[f][g][r] = 0.f;

    // per-thread ldmatrix source offsets (byte offsets within tile, pre-swizzle)
    // A frag f (m16): row = wm*64 + f*16 + ((lane>>3)&1)*8 + (lane&7), kb = (lane>>4)*16
    const int a_row_in = ((lane >> 3) & 1) * 8 + (lane & 7);
    const int a_kb     = (lane >> 4) * 16;
    // B x4 pair p (two n-frags): row = wn*32 + p*16 + (lane>>4)*8 + (lane&7), kb = ((lane>>3)&1)*16
    const int b_row_in = (lane >> 4) * 8 + (lane & 7);
    const int b_kb     = ((lane >> 3) & 1) * 16;

    for (int c = 0; c < nch; c++) {
        asm volatile("cp.async.wait_group 1;" ::: "memory");
        __syncthreads();

        if (c + 2 < nch) load_chunk(c + 2);

        const uint32_t sA = base + (c % NSTAGE) * STAGE_SZ;
        const uint32_t sB = sA + 16384;

        #pragma unroll
        for (int ks = 0; ks < 4; ks++) {
            uint32_t a[4][4], b[2][4];
            #pragma unroll
            for (int f = 0; f < 4; f++) {
                int row = wm * 64 + f * 16 + a_row_in;
                ldsm_x4(a[f], sA + SWZ(row * 128 + ks * 32 + a_kb));
            }
            #pragma unroll
            for (int p = 0; p < 2; p++) {
                int row = wn * 32 + p * 16 + b_row_in;
                ldsm_x4(b[p], sB + SWZ(row * 128 + ks * 32 + b_kb));
            }
            #pragma unroll
            for (int f = 0; f < 4; f++)
                #pragma unroll
                for (int r = 0; r < 4; r++) a[f][r] = f2tf(a[f][r]);
            #pragma unroll
            for (int p = 0; p < 2; p++)
                #pragma unroll
                for (int r = 0; r < 4; r++) b[p][r] = f2tf(b[p][r]);

            #pragma unroll
            for (int f = 0; f < 4; f++)
                #pragma unroll
                for (int g = 0; g < 4; g++)
                    mma_tf32(acc[f][g], a[f], b[g >> 1][(g & 1) * 2], b[g >> 1][(g & 1) * 2 + 1]);
        }
        __syncthreads();
    }

    // epilogue
    const int col_in = 2 * (lane & 3);
    #pragma unroll
    for (int g = 0; g < 4; g++) {
        const int col = bn * 128 + wn * 32 + g * 8 + col_in;
        const float b0 = bias[col], b1 = bias[col + 1];
        #pragma unroll
        for (int f = 0; f < 4; f++) {
            const size_t r0 = (size_t)bm * 128 + wm * 64 + f * 16 + (lane >> 2);
            float2 v0 = make_float2(acc[f][g][0] + b0, acc[f][g][1] + b1);
            float2 v1 = make_float2(acc[f][g][2] + b0, acc[f][g][3] + b1);
            *(float2*)(C + r0 * N + col)       = v0;
            *(float2*)(C + (r0 + 8) * N + col) = v1;
        }
    }
}

// ---------------------------------------------------------------------------
// K1: (b,c,t,h,w) -> LayerNorm over c -> g_nrm[(b*1024+h*32+w)*16 + t][c]
// ---------------------------------------------------------------------------
__global__ __launch_bounds__(256) void k1_ln(const float* __restrict__ x,
                                             const float* __restrict__ gamma,
                                             const float* __restrict__ beta,
                                             float* __restrict__ nrm) {
    int bid = blockIdx.x;
    int b = bid >> 9;
    int t = (bid >> 5) & 15;
    int h = bid & 31;
    int tid = threadIdx.x;
    int lane = tid & 31, r = tid >> 5;

    size_t base = (size_t)b * (CC * TT * HH * WW) + (size_t)t * (HH * WW) + (size_t)h * WW;

    float s = 0.f, s2 = 0.f;
    for (int cc = r; cc < CC; cc += 8) {
        float v = x[base + (size_t)cc * (TT*HH*WW) + lane];
        s += v; s2 += v * v;
    }
    __shared__ float red0[8][32], red1[8][32];
    __shared__ float mu_s[32], rs_s[32];
    red0[r][lane] = s; red1[r][lane] = s2;
    __syncthreads();
    if (tid < 32) {
        float a = 0.f, q = 0.f;
        #pragma unroll
        for (int i = 0; i < 8; i++) { a += red0[i][tid]; q += red1[i][tid]; }
        float mu = a * (1.f / CC);
        float var = q * (1.f / CC) - mu * mu;
        mu_s[tid] = mu;
        rs_s[tid] = rsqrtf(var + 1e-5f);
    }
    __syncthreads();

    size_t obase = ((size_t)(b * 1024 + h * 32) * TT + t) * CC;

    __shared__ float tile[128 * 33];
    for (int c0 = 0; c0 < CC; c0 += 128) {
        __syncthreads();
        for (int e = tid; e < 128 * 32; e += 256) {
            int cc = e >> 5, ww = e & 31;
            tile[cc * 33 + ww] = x[base + (size_t)(c0 + cc) * (TT*HH*WW) + ww];
        }
        __syncthreads();
        for (int e = tid; e < 128 * 32; e += 256) {
            int ww = e >> 7, cc = e & 127;
            float v = (tile[cc * 33 + ww] - mu_s[ww]) * rs_s[ww] * gamma[c0 + cc] + beta[c0 + cc];
            nrm[obase + (size_t)ww * (TT * CC) + c0 + cc] = v;
        }
    }
}

// ---------------------------------------------------------------------------
// K3: attention per (B-seq, head). t=16, ch=64.
// ---------------------------------------------------------------------------
__global__ __launch_bounds__(256) void k3_attn(const float* __restrict__ qkv,
                                               const float* __restrict__ k_table,
                                               const float* __restrict__ v_table,
                                               float* __restrict__ aout) {
    int blk = blockIdx.x;
    int Bidx = blk >> 3;
    int hh = blk & 7;
    int tid = threadIdx.x;

    __shared__ float qs[16 * 65], ks[16 * 65], vs[16 * 65];
    __shared__ float ktab[31 * 65], vtab[31 * 65];
    __shared__ float attn[16 * 17];

    size_t rowbase = (size_t)Bidx * TT * (3 * CC) + hh * CH;
    for (int e = tid; e < 16 * 64; e += 256) {
        int i = e >> 6, cc = e & 63;
        size_t off = rowbase + (size_t)i * (3 * CC) + cc;
        qs[i * 65 + cc] = qkv[off];
        ks[i * 65 + cc] = qkv[off + CC];
        vs[i * 65 + cc] = qkv[off + 2 * CC];
    }
    for (int e = tid; e < 31 * 64; e += 256) {
        int rr = e >> 6, cc = e & 63;
        ktab[rr * 65 + cc] = k_table[(49 + rr) * CH + cc];
        vtab[rr * 65 + cc] = v_table[(49 + rr) * CH + cc];
    }
    __syncthreads();

    {
        int i = tid >> 4, j = tid & 15;
        const float* kr = &ktab[(j - i + 15) * 65];
        const float* qr = &qs[i * 65];
        const float* krow = &ks[j * 65];
        float s = 0.f;
        #pragma unroll
        for (int cc = 0; cc < 64; cc++)
            s = fmaf(qr[cc], krow[cc] + kr[cc], s);
        s *= 0.125f;

        float m = s;
        #pragma unroll
        for (int o = 8; o; o >>= 1)
            m = fmaxf(m, __shfl_xor_sync(0xffffffffu, m, o));
        float e1 = expf(s - m);
        float sum = e1;
        #pragma unroll
        for (int o = 8; o; o >>= 1)
            sum += __shfl_xor_sync(0xffffffffu, sum, o);
        attn[i * 17 + j] = e1 / sum;
    }
    __syncthreads();

    {
        int oi = tid >> 4;
        int cb = (tid & 15) * 4;
        float o0 = 0.f, o1 = 0.f, o2 = 0.f, o3 = 0.f;
        #pragma unroll
        for (int jj = 0; jj < 16; jj++) {
            float aw = attn[oi * 17 + jj];
            const float* vr = &vtab[(jj - oi + 15) * 65 + cb];
            const float* vv = &vs[jj * 65 + cb];
            o0 = fmaf(aw, vv[0] + vr[0], o0);
            o1 = fmaf(aw, vv[1] + vr[1], o1);
            o2 = fmaf(aw, vv[2] + vr[2], o2);
            o3 = fmaf(aw, vv[3] + vr[3], o3);
        }
        float4 ov = make_float4(o0, o1, o2, o3);
        *(float4*)(aout + (size_t)(Bidx * TT + oi) * CC + hh * CH + cb) = ov;
    }
}

// ---------------------------------------------------------------------------
// K5: out = x + transpose-back(proj_seq)
// ---------------------------------------------------------------------------
__global__ __launch_bounds__(256) void k5_resid(const float* __restrict__ x,
                                                const float* __restrict__ oseq,
                                                float* __restrict__ out) {
    int bid = blockIdx.x;
    int b = bid >> 9;
    int t = (bid >> 5) & 15;
    int h = bid & 31;
    int tid = threadIdx.x;

    size_t base  = (size_t)b * (CC * TT * HH * WW) + (size_t)t * (HH * WW) + (size_t)h * WW;
    size_t obase = ((size_t)(b * 1024 + h * 32) * TT + t) * CC;

    __shared__ float tile[128 * 33];
    for (int c0 = 0; c0 < CC; c0 += 128) {
        __syncthreads();
        for (int e = tid; e < 128 * 32; e += 256) {
            int ww = e >> 7, cc = e & 127;
            tile[cc * 33 + ww] = oseq[obase + (size_t)ww * (TT * CC) + c0 + cc];
        }
        __syncthreads();
        for (int e = tid; e < 128 * 32; e += 256) {
            int cc = e >> 5, ww = e & 31;
            size_t gi = base + (size_t)(c0 + cc) * (TT*HH*WW) + ww;
            out[gi] = x[gi] + tile[cc * 33 + ww];
        }
    }
}

// ---------------------------------------------------------------------------
extern "C" void kernel_launch(void* const* d_in, const int* in_sizes, int n_in,
                              void* d_out, int out_size) {
    const float* x       = (const float*)d_in[0];
    const float* ln_g    = (const float*)d_in[1];
    const float* ln_b    = (const float*)d_in[2];
    const float* qkv_w   = (const float*)d_in[3];
    const float* qkv_b   = (const float*)d_in[4];
    const float* k_table = (const float*)d_in[5];
    const float* v_table = (const float*)d_in[6];
    const float* proj_w  = (const float*)d_in[7];
    const float* proj_b  = (const float*)d_in[8];
    float* out = (float*)d_out;

    void *p_nrm_v, *p_qkv_v, *p_att_v;
    cudaGetSymbolAddress(&p_nrm_v, g_nrm);
    cudaGetSymbolAddress(&p_qkv_v, g_qkv);
    cudaGetSymbolAddress(&p_att_v, g_att);
    float* p_nrm = (float*)p_nrm_v;
    float* p_qkv = (float*)p_qkv_v;
    float* p_att = (float*)p_att_v;

    cudaFuncSetAttribute(tc_gemm, cudaFuncAttributeMaxDynamicSharedMemorySize, GSMEM_SZ);

    // K1: layernorm + layout transform
    k1_ln<<<BB * TT * HH, 256>>>(x, ln_g, ln_b, p_nrm);

    // K2: qkv = nrm @ qkv_w^T + qkv_b   (32768 x 1536 x 512)
    {
        dim3 grid(3 * CC / 128, ROWS / 128);
        tc_gemm<<<grid, 256, GSMEM_SZ>>>(p_nrm, qkv_w, qkv_b, p_qkv, ROWS, 3 * CC, CC);
    }

    // K3: attention per (seq, head)
    k3_attn<<<BSEQ * NH, 256>>>(p_qkv, k_table, v_table, p_att);

    // K4: proj = att @ proj_w^T + proj_b  (32768 x 512 x 512)
    {
        dim3 grid(CC / 128, ROWS / 128);
        tc_gemm<<<grid, 256, GSMEM_SZ>>>(p_att, proj_w, proj_b, p_nrm, ROWS, CC, CC);
    }

    // K5: residual add + transform back
    k5_resid<<<BB * TT * HH, 256>>>(x, p_nrm, out);
}

// round 6
// speedup vs baseline: 2.8980x; 1.2125x over previous
#include <cuda_runtime.h>
#include <cstdint>

#define BB   2
#define CC   512
#define TT   16
#define HH   32
#define WW   32
#define NH   8
#define CH   64
#define BSEQ (BB*HH*WW)     // 2048
#define ROWS (BSEQ*TT)      // 32768

__device__ float g_nrm[(size_t)ROWS * CC];
__device__ float g_qkv[(size_t)ROWS * 3 * CC];
__device__ float g_att[(size_t)ROWS * CC];
__device__ float g_wq[(size_t)3 * CC * CC];   // tf32-rounded qkv_w
__device__ float g_wp[(size_t)CC * CC];       // tf32-rounded proj_w

// ---------------------------------------------------------------------------
__device__ __forceinline__ uint32_t smem_u32(const void* p) {
    uint32_t a;
    asm("{ .reg .u64 t; cvta.to.shared.u64 t, %1; cvt.u32.u64 %0, t; }" : "=r"(a) : "l"(p));
    return a;
}
#define SWZ(o) ((o) ^ ((((uint32_t)(o)) >> 3) & 0x70))

__device__ __forceinline__ void cpasync16(uint32_t dst, const void* src) {
    asm volatile("cp.async.cg.shared.global [%0], [%1], 16;" :: "r"(dst), "l"(src));
}
__device__ __forceinline__ void ldsm_x4(uint32_t* r, uint32_t addr) {
    asm volatile("ldmatrix.sync.aligned.m8n8.x4.shared.b16 {%0,%1,%2,%3}, [%4];"
                 : "=r"(r[0]), "=r"(r[1]), "=r"(r[2]), "=r"(r[3]) : "r"(addr));
}
__device__ __forceinline__ float f2tf_f(float x) {
    uint32_t y;
    asm("cvt.rna.tf32.f32 %0, %1;" : "=r"(y) : "r"(__float_as_uint(x)));
    return __uint_as_float(y);
}
__device__ __forceinline__ void mma_tf32(float* c, const uint32_t* a, uint32_t b0, uint32_t b1) {
    asm volatile(
        "mma.sync.aligned.m16n8k8.row.col.f32.tf32.tf32.f32 "
        "{%0,%1,%2,%3}, {%4,%5,%6,%7}, {%8,%9}, {%0,%1,%2,%3};"
        : "+f"(c[0]), "+f"(c[1]), "+f"(c[2]), "+f"(c[3])
        : "r"(a[0]), "r"(a[1]), "r"(a[2]), "r"(a[3]), "r"(b0), "r"(b1));
}

// ---------------------------------------------------------------------------
// Weight pre-round to tf32 (rna)
// ---------------------------------------------------------------------------
__global__ __launch_bounds__(256) void wcvt(const float* __restrict__ qkv_w,
                                            const float* __restrict__ proj_w,
                                            float* __restrict__ wq,
                                            float* __restrict__ wp) {
    int i = blockIdx.x * 256 + threadIdx.x;
    if (i < 3 * CC * CC) wq[i] = f2tf_f(qkv_w[i]);
    if (i < CC * CC)     wp[i] = f2tf_f(proj_w[i]);
}

// ---------------------------------------------------------------------------
// TF32 tensor GEMM-NT: C[M,N] = A[M,K] @ W[N,K]^T + bias
// A, W already tf32-rounded. CTA 128x128, BK=32, 8 warps (64x32 each),
// 3-stage cp.async pipeline, 2 CTAs/SM.
// ---------------------------------------------------------------------------
#define NSTAGE   3
#define STAGE_SZ 32768               // A 16KB + B 16KB
#define GSMEM_SZ (NSTAGE*STAGE_SZ)

__global__ __launch_bounds__(256, 2) void tc_gemm(const float* __restrict__ A,
                                                  const float* __restrict__ W,
                                                  const float* __restrict__ bias,
                                                  float* __restrict__ C,
                                                  int M, int N, int K) {
    extern __shared__ __align__(1024) char smraw[];
    const uint32_t base = smem_u32(smraw);

    const int tid  = threadIdx.x;
    const int wid  = tid >> 5, lane = tid & 31;
    const int wm   = wid & 1, wn = wid >> 1;       // warp tile: (wm*64, wn*32)
    const int bn   = blockIdx.x, bm = blockIdx.y;
    const int nch  = K >> 5;

    // cp.async per-thread precompute (same (r,c16) pattern for A and B)
    uint32_t st_off[4];
    const float* ga[4];
    const float* gw[4];
    #pragma unroll
    for (int it = 0; it < 4; it++) {
        int idx = tid + it * 256;
        int r = idx >> 3, c16 = idx & 7;
        st_off[it] = SWZ((uint32_t)(r * 128 + c16 * 16));
        ga[it] = A + (size_t)(bm * 128 + r) * K + c16 * 4;
        gw[it] = W + (size_t)(bn * 128 + r) * K + c16 * 4;
    }

    auto load_chunk = [&](int l) {
        const int k0 = l << 5;
        const uint32_t sA = base + (l % NSTAGE) * STAGE_SZ;
        const uint32_t sB = sA + 16384;
        #pragma unroll
        for (int it = 0; it < 4; it++) {
            cpasync16(sA + st_off[it], ga[it] + k0);
            cpasync16(sB + st_off[it], gw[it] + k0);
        }
        asm volatile("cp.async.commit_group;" ::: "memory");
    };

    load_chunk(0);
    load_chunk(1);

    // ldmatrix per-thread swizzled base offsets (ks=0); per-ks addr = off ^ (ks<<5)
    const int a_row_in = ((lane >> 3) & 1) * 8 + (lane & 7);
    const int a_kb     = (lane >> 4) * 16;
    const int b_row_in = (lane >> 4) * 8 + (lane & 7);
    const int b_kb     = ((lane >> 3) & 1) * 16;
    uint32_t a_off[4], b_off[2];
    #pragma unroll
    for (int f = 0; f < 4; f++) {
        int row = wm * 64 + f * 16 + a_row_in;
        a_off[f] = (uint32_t)(row * 128 + (a_kb ^ ((row & 7) << 4)));
    }
    #pragma unroll
    for (int p = 0; p < 2; p++) {
        int row = wn * 32 + p * 16 + b_row_in;
        b_off[p] = (uint32_t)(row * 128 + (b_kb ^ ((row & 7) << 4)));
    }

    float acc[4][4][4];
    #pragma unroll
    for (int f = 0; f < 4; f++)
        #pragma unroll
        for (int g = 0; g < 4; g++)
            #pragma unroll
            for (int r = 0; r < 4; r++) acc[f][g][r] = 0.f;

    for (int c = 0; c < nch; c++) {
        asm volatile("cp.async.wait_group 1;" ::: "memory");
        __syncthreads();

        if (c + 2 < nch) load_chunk(c + 2);

        const uint32_t sA = base + (c % NSTAGE) * STAGE_SZ;
        const uint32_t sB = sA + 16384;

        #pragma unroll
        for (int ks = 0; ks < 4; ks++) {
            uint32_t a[4][4], b[2][4];
            #pragma unroll
            for (int f = 0; f < 4; f++)
                ldsm_x4(a[f], sA + (a_off[f] ^ (ks << 5)));
            #pragma unroll
            for (int p = 0; p < 2; p++)
                ldsm_x4(b[p], sB + (b_off[p] ^ (ks << 5)));

            #pragma unroll
            for (int f = 0; f < 4; f++)
                #pragma unroll
                for (int g = 0; g < 4; g++)
                    mma_tf32(acc[f][g], a[f], b[g >> 1][(g & 1) * 2], b[g >> 1][(g & 1) * 2 + 1]);
        }
        __syncthreads();
    }

    // epilogue
    const int col_in = 2 * (lane & 3);
    #pragma unroll
    for (int g = 0; g < 4; g++) {
        const int col = bn * 128 + wn * 32 + g * 8 + col_in;
        const float b0 = bias[col], b1 = bias[col + 1];
        #pragma unroll
        for (int f = 0; f < 4; f++) {
            const size_t r0 = (size_t)bm * 128 + wm * 64 + f * 16 + (lane >> 2);
            float2 v0 = make_float2(acc[f][g][0] + b0, acc[f][g][1] + b1);
            float2 v1 = make_float2(acc[f][g][2] + b0, acc[f][g][3] + b1);
            *(float2*)(C + r0 * N + col)       = v0;
            *(float2*)(C + (r0 + 8) * N + col) = v1;
        }
    }
}

// ---------------------------------------------------------------------------
// K1: (b,c,t,h,w) -> LayerNorm over c -> g_nrm[(b*1024+h*32+w)*16 + t][c]
// Single pass: whole 512(c) x 32(w) tile in smem; output tf32-rounded.
// ---------------------------------------------------------------------------
#define K1_SMEM (512 * 33 * 4)

__global__ __launch_bounds__(256) void k1_ln(const float* __restrict__ x,
                                             const float* __restrict__ gamma,
                                             const float* __restrict__ beta,
                                             float* __restrict__ nrm) {
    extern __shared__ float tile[];          // [512][33]
    int bid = blockIdx.x;
    int b = bid >> 9;
    int t = (bid >> 5) & 15;
    int h = bid & 31;
    int tid = threadIdx.x;
    int lane = tid & 31, r = tid >> 5;

    size_t xbase = (size_t)b * (CC * TT * HH * WW) + (size_t)t * (HH * WW) + (size_t)h * WW;

    // load whole tile (coalesced over w)
    #pragma unroll
    for (int it = 0; it < 64; it++) {
        int e = tid + it * 256;
        int cc = e >> 5, ww = e & 31;
        tile[cc * 33 + ww] = x[xbase + (size_t)cc * (TT*HH*WW) + ww];
    }
    __syncthreads();

    // stats: thread (r, lane) sums cc = r, r+8, ... for w=lane
    float s = 0.f, s2 = 0.f;
    for (int cc = r; cc < CC; cc += 8) {
        float v = tile[cc * 33 + lane];
        s += v; s2 += v * v;
    }
    __shared__ float red0[8][32], red1[8][32];
    __shared__ float mu_s[32], rs_s[32];
    red0[r][lane] = s; red1[r][lane] = s2;
    __syncthreads();
    if (tid < 32) {
        float a = 0.f, q = 0.f;
        #pragma unroll
        for (int i = 0; i < 8; i++) { a += red0[i][tid]; q += red1[i][tid]; }
        float mu = a * (1.f / CC);
        float var = q * (1.f / CC) - mu * mu;
        mu_s[tid] = mu;
        rs_s[tid] = rsqrtf(var + 1e-5f);
    }
    __syncthreads();

    size_t obase = ((size_t)(b * 1024 + h * 32) * TT + t) * CC;

    // write: e -> (w = e>>9, cc = e&511); coalesced over cc
    #pragma unroll
    for (int it = 0; it < 64; it++) {
        int e = tid + it * 256;
        int ww = e >> 9, cc = e & 511;
        float v = (tile[cc * 33 + ww] - mu_s[ww]) * rs_s[ww] * gamma[cc] + beta[cc];
        nrm[obase + (size_t)ww * (TT * CC) + cc] = f2tf_f(v);
    }
}

// ---------------------------------------------------------------------------
// K3: attention per (B-seq, head). t=16, ch=64. Output tf32-rounded.
// ---------------------------------------------------------------------------
__global__ __launch_bounds__(256) void k3_attn(const float* __restrict__ qkv,
                                               const float* __restrict__ k_table,
                                               const float* __restrict__ v_table,
                                               float* __restrict__ aout) {
    int blk = blockIdx.x;
    int Bidx = blk >> 3;
    int hh = blk & 7;
    int tid = threadIdx.x;

    __shared__ float qs[16 * 65], ks[16 * 65], vs[16 * 65];
    __shared__ float ktab[31 * 65], vtab[31 * 65];
    __shared__ float attn[16 * 17];

    size_t rowbase = (size_t)Bidx * TT * (3 * CC) + hh * CH;
    for (int e = tid; e < 16 * 64; e += 256) {
        int i = e >> 6, cc = e & 63;
        size_t off = rowbase + (size_t)i * (3 * CC) + cc;
        qs[i * 65 + cc] = qkv[off];
        ks[i * 65 + cc] = qkv[off + CC];
        vs[i * 65 + cc] = qkv[off + 2 * CC];
    }
    for (int e = tid; e < 31 * 64; e += 256) {
        int rr = e >> 6, cc = e & 63;
        ktab[rr * 65 + cc] = k_table[(49 + rr) * CH + cc];
        vtab[rr * 65 + cc] = v_table[(49 + rr) * CH + cc];
    }
    __syncthreads();

    {
        int i = tid >> 4, j = tid & 15;
        const float* kr = &ktab[(j - i + 15) * 65];
        const float* qr = &qs[i * 65];
        const float* krow = &ks[j * 65];
        float s = 0.f;
        #pragma unroll
        for (int cc = 0; cc < 64; cc++)
            s = fmaf(qr[cc], krow[cc] + kr[cc], s);
        s *= 0.125f;

        float m = s;
        #pragma unroll
        for (int o = 8; o; o >>= 1)
            m = fmaxf(m, __shfl_xor_sync(0xffffffffu, m, o));
        float e1 = expf(s - m);
        float sum = e1;
        #pragma unroll
        for (int o = 8; o; o >>= 1)
            sum += __shfl_xor_sync(0xffffffffu, sum, o);
        attn[i * 17 + j] = e1 / sum;
    }
    __syncthreads();

    {
        int oi = tid >> 4;
        int cb = (tid & 15) * 4;
        float o0 = 0.f, o1 = 0.f, o2 = 0.f, o3 = 0.f;
        #pragma unroll
        for (int jj = 0; jj < 16; jj++) {
            float aw = attn[oi * 17 + jj];
            const float* vr = &vtab[(jj - oi + 15) * 65 + cb];
            const float* vv = &vs[jj * 65 + cb];
            o0 = fmaf(aw, vv[0] + vr[0], o0);
            o1 = fmaf(aw, vv[1] + vr[1], o1);
            o2 = fmaf(aw, vv[2] + vr[2], o2);
            o3 = fmaf(aw, vv[3] + vr[3], o3);
        }
        float4 ov = make_float4(f2tf_f(o0), f2tf_f(o1), f2tf_f(o2), f2tf_f(o3));
        *(float4*)(aout + (size_t)(Bidx * TT + oi) * CC + hh * CH + cb) = ov;
    }
}

// ---------------------------------------------------------------------------
// K5: out = x + transpose-back(proj_seq)
// ---------------------------------------------------------------------------
__global__ __launch_bounds__(256) void k5_resid(const float* __restrict__ x,
                                                const float* __restrict__ oseq,
                                                float* __restrict__ out) {
    int bid = blockIdx.x;
    int b = bid >> 9;
    int t = (bid >> 5) & 15;
    int h = bid & 31;
    int tid = threadIdx.x;

    size_t base  = (size_t)b * (CC * TT * HH * WW) + (size_t)t * (HH * WW) + (size_t)h * WW;
    size_t obase = ((size_t)(b * 1024 + h * 32) * TT + t) * CC;

    __shared__ float tile[128 * 33];
    for (int c0 = 0; c0 < CC; c0 += 128) {
        __syncthreads();
        for (int e = tid; e < 128 * 32; e += 256) {
            int ww = e >> 7, cc = e & 127;
            tile[cc * 33 + ww] = oseq[obase + (size_t)ww * (TT * CC) + c0 + cc];
        }
        __syncthreads();
        for (int e = tid; e < 128 * 32; e += 256) {
            int cc = e >> 5, ww = e & 31;
            size_t gi = base + (size_t)(c0 + cc) * (TT*HH*WW) + ww;
            out[gi] = x[gi] + tile[cc * 33 + ww];
        }
    }
}

// ---------------------------------------------------------------------------
extern "C" void kernel_launch(void* const* d_in, const int* in_sizes, int n_in,
                              void* d_out, int out_size) {
    const float* x       = (const float*)d_in[0];
    const float* ln_g    = (const float*)d_in[1];
    const float* ln_b    = (const float*)d_in[2];
    const float* qkv_w   = (const float*)d_in[3];
    const float* qkv_b   = (const float*)d_in[4];
    const float* k_table = (const float*)d_in[5];
    const float* v_table = (const float*)d_in[6];
    const float* proj_w  = (const float*)d_in[7];
    const float* proj_b  = (const float*)d_in[8];
    float* out = (float*)d_out;

    void *p_nrm_v, *p_qkv_v, *p_att_v, *p_wq_v, *p_wp_v;
    cudaGetSymbolAddress(&p_nrm_v, g_nrm);
    cudaGetSymbolAddress(&p_qkv_v, g_qkv);
    cudaGetSymbolAddress(&p_att_v, g_att);
    cudaGetSymbolAddress(&p_wq_v, g_wq);
    cudaGetSymbolAddress(&p_wp_v, g_wp);
    float* p_nrm = (float*)p_nrm_v;
    float* p_qkv = (float*)p_qkv_v;
    float* p_att = (float*)p_att_v;
    float* p_wq  = (float*)p_wq_v;
    float* p_wp  = (float*)p_wp_v;

    cudaFuncSetAttribute(tc_gemm, cudaFuncAttributeMaxDynamicSharedMemorySize, GSMEM_SZ);
    cudaFuncSetAttribute(k1_ln, cudaFuncAttributeMaxDynamicSharedMemorySize, K1_SMEM);

    // W0: pre-round weights to tf32
    wcvt<<<(3 * CC * CC + 255) / 256, 256>>>(qkv_w, proj_w, p_wq, p_wp);

    // K1: layernorm + layout transform (tf32-rounded output)
    k1_ln<<<BB * TT * HH, 256, K1_SMEM>>>(x, ln_g, ln_b, p_nrm);

    // K2: qkv = nrm @ qkv_w^T + qkv_b   (32768 x 1536 x 512)
    {
        dim3 grid(3 * CC / 128, ROWS / 128);
        tc_gemm<<<grid, 256, GSMEM_SZ>>>(p_nrm, p_wq, qkv_b, p_qkv, ROWS, 3 * CC, CC);
    }

    // K3: attention per (seq, head)
    k3_attn<<<BSEQ * NH, 256>>>(p_qkv, k_table, v_table, p_att);

    // K4: proj = att @ proj_w^T + proj_b  (32768 x 512 x 512)
    {
        dim3 grid(CC / 128, ROWS / 128);
        tc_gemm<<<grid, 256, GSMEM_SZ>>>(p_att, p_wp, proj_b, p_nrm, ROWS, CC, CC);
    }

    // K5: residual add + transform back
    k5_resid<<<BB * TT * HH, 256>>>(x, p_nrm, out);
}

// round 7
// speedup vs baseline: 3.9542x; 1.3645x over previous
#include <cuda_runtime.h>
#include <cstdint>

#define BB   2
#define CC   512
#define TT   16
#define HH   32
#define WW   32
#define NH   8
#define CH   64
#define BSEQ (BB*HH*WW)     // 2048
#define ROWS (BSEQ*TT)      // 32768

__device__ float g_nrm[(size_t)ROWS * CC];
__device__ float g_qkv[(size_t)ROWS * 3 * CC];
__device__ float g_att[(size_t)ROWS * CC];
__device__ float g_wq[(size_t)3 * CC * CC];
__device__ float g_wp[(size_t)CC * CC];

// ---------------------------------------------------------------------------
__device__ __forceinline__ uint32_t smem_u32(const void* p) {
    uint32_t a;
    asm("{ .reg .u64 t; cvta.to.shared.u64 t, %1; cvt.u32.u64 %0, t; }" : "=r"(a) : "l"(p));
    return a;
}
#define SWZ(o) ((o) ^ ((((uint32_t)(o)) >> 3) & 0x70))

__device__ __forceinline__ void cpasync16(uint32_t dst, const void* src) {
    asm volatile("cp.async.cg.shared.global [%0], [%1], 16;" :: "r"(dst), "l"(src));
}
__device__ __forceinline__ void ldsm_x4(uint32_t* r, uint32_t addr) {
    asm volatile("ldmatrix.sync.aligned.m8n8.x4.shared.b16 {%0,%1,%2,%3}, [%4];"
                 : "=r"(r[0]), "=r"(r[1]), "=r"(r[2]), "=r"(r[3]) : "r"(addr));
}
__device__ __forceinline__ float f2tf_f(float x) {
    uint32_t y;
    asm("cvt.rna.tf32.f32 %0, %1;" : "=r"(y) : "r"(__float_as_uint(x)));
    return __uint_as_float(y);
}
__device__ __forceinline__ void mma_tf32(float* c, const uint32_t* a, uint32_t b0, uint32_t b1) {
    asm volatile(
        "mma.sync.aligned.m16n8k8.row.col.f32.tf32.tf32.f32 "
        "{%0,%1,%2,%3}, {%4,%5,%6,%7}, {%8,%9}, {%0,%1,%2,%3};"
        : "+f"(c[0]), "+f"(c[1]), "+f"(c[2]), "+f"(c[3])
        : "r"(a[0]), "r"(a[1]), "r"(a[2]), "r"(a[3]), "r"(b0), "r"(b1));
}

// ---------------------------------------------------------------------------
__global__ __launch_bounds__(256) void wcvt(const float* __restrict__ qkv_w,
                                            const float* __restrict__ proj_w,
                                            float* __restrict__ wq,
                                            float* __restrict__ wp) {
    int i = blockIdx.x * 256 + threadIdx.x;
    if (i < 3 * CC * CC) wq[i] = f2tf_f(qkv_w[i]);
    if (i < CC * CC)     wp[i] = f2tf_f(proj_w[i]);
}

// ---------------------------------------------------------------------------
// TF32 tensor GEMM-NT (unchanged from round 6)
// ---------------------------------------------------------------------------
#define NSTAGE   3
#define STAGE_SZ 32768
#define GSMEM_SZ (NSTAGE*STAGE_SZ)

__global__ __launch_bounds__(256, 2) void tc_gemm(const float* __restrict__ A,
                                                  const float* __restrict__ W,
                                                  const float* __restrict__ bias,
                                                  float* __restrict__ C,
                                                  int M, int N, int K) {
    extern __shared__ __align__(1024) char smraw[];
    const uint32_t base = smem_u32(smraw);

    const int tid  = threadIdx.x;
    const int wid  = tid >> 5, lane = tid & 31;
    const int wm   = wid & 1, wn = wid >> 1;
    const int bn   = blockIdx.x, bm = blockIdx.y;
    const int nch  = K >> 5;

    uint32_t st_off[4];
    const float* ga[4];
    const float* gw[4];
    #pragma unroll
    for (int it = 0; it < 4; it++) {
        int idx = tid + it * 256;
        int r = idx >> 3, c16 = idx & 7;
        st_off[it] = SWZ((uint32_t)(r * 128 + c16 * 16));
        ga[it] = A + (size_t)(bm * 128 + r) * K + c16 * 4;
        gw[it] = W + (size_t)(bn * 128 + r) * K + c16 * 4;
    }

    auto load_chunk = [&](int l) {
        const int k0 = l << 5;
        const uint32_t sA = base + (l % NSTAGE) * STAGE_SZ;
        const uint32_t sB = sA + 16384;
        #pragma unroll
        for (int it = 0; it < 4; it++) {
            cpasync16(sA + st_off[it], ga[it] + k0);
            cpasync16(sB + st_off[it], gw[it] + k0);
        }
        asm volatile("cp.async.commit_group;" ::: "memory");
    };

    load_chunk(0);
    load_chunk(1);

    const int a_row_in = ((lane >> 3) & 1) * 8 + (lane & 7);
    const int a_kb     = (lane >> 4) * 16;
    const int b_row_in = (lane >> 4) * 8 + (lane & 7);
    const int b_kb     = ((lane >> 3) & 1) * 16;
    uint32_t a_off[4], b_off[2];
    #pragma unroll
    for (int f = 0; f < 4; f++) {
        int row = wm * 64 + f * 16 + a_row_in;
        a_off[f] = (uint32_t)(row * 128 + (a_kb ^ ((row & 7) << 4)));
    }
    #pragma unroll
    for (int p = 0; p < 2; p++) {
        int row = wn * 32 + p * 16 + b_row_in;
        b_off[p] = (uint32_t)(row * 128 + (b_kb ^ ((row & 7) << 4)));
    }

    float acc[4][4][4];
    #pragma unroll
    for (int f = 0; f < 4; f++)
        #pragma unroll
        for (int g = 0; g < 4; g++)
            #pragma unroll
            for (int r = 0; r < 4; r++) acc[f][g][r] = 0.f;

    for (int c = 0; c < nch; c++) {
        asm volatile("cp.async.wait_group 1;" ::: "memory");
        __syncthreads();

        if (c + 2 < nch) load_chunk(c + 2);

        const uint32_t sA = base + (c % NSTAGE) * STAGE_SZ;
        const uint32_t sB = sA + 16384;

        #pragma unroll
        for (int ks = 0; ks < 4; ks++) {
            uint32_t a[4][4], b[2][4];
            #pragma unroll
            for (int f = 0; f < 4; f++)
                ldsm_x4(a[f], sA + (a_off[f] ^ (ks << 5)));
            #pragma unroll
            for (int p = 0; p < 2; p++)
                ldsm_x4(b[p], sB + (b_off[p] ^ (ks << 5)));

            #pragma unroll
            for (int f = 0; f < 4; f++)
                #pragma unroll
                for (int g = 0; g < 4; g++)
                    mma_tf32(acc[f][g], a[f], b[g >> 1][(g & 1) * 2], b[g >> 1][(g & 1) * 2 + 1]);
        }
        __syncthreads();
    }

    const int col_in = 2 * (lane & 3);
    #pragma unroll
    for (int g = 0; g < 4; g++) {
        const int col = bn * 128 + wn * 32 + g * 8 + col_in;
        const float b0 = bias[col], b1 = bias[col + 1];
        #pragma unroll
        for (int f = 0; f < 4; f++) {
            const size_t r0 = (size_t)bm * 128 + wm * 64 + f * 16 + (lane >> 2);
            float2 v0 = make_float2(acc[f][g][0] + b0, acc[f][g][1] + b1);
            float2 v1 = make_float2(acc[f][g][2] + b0, acc[f][g][3] + b1);
            *(float2*)(C + r0 * N + col)       = v0;
            *(float2*)(C + (r0 + 8) * N + col) = v1;
        }
    }
}

// ---------------------------------------------------------------------------
// K1: (b,c,t,h,w) -> LayerNorm over c -> g_nrm[(b*1024+h*32+w)*16 + t][c]
// ---------------------------------------------------------------------------
#define K1_SMEM (512 * 33 * 4)

__global__ __launch_bounds__(256) void k1_ln(const float* __restrict__ x,
                                             const float* __restrict__ gamma,
                                             const float* __restrict__ beta,
                                             float* __restrict__ nrm) {
    extern __shared__ float tile[];
    int bid = blockIdx.x;
    int b = bid >> 9;
    int t = (bid >> 5) & 15;
    int h = bid & 31;
    int tid = threadIdx.x;
    int lane = tid & 31, r = tid >> 5;

    size_t xbase = (size_t)b * (CC * TT * HH * WW) + (size_t)t * (HH * WW) + (size_t)h * WW;

    #pragma unroll
    for (int it = 0; it < 64; it++) {
        int e = tid + it * 256;
        int cc = e >> 5, ww = e & 31;
        tile[cc * 33 + ww] = x[xbase + (size_t)cc * (TT*HH*WW) + ww];
    }
    __syncthreads();

    float s = 0.f, s2 = 0.f;
    for (int cc = r; cc < CC; cc += 8) {
        float v = tile[cc * 33 + lane];
        s += v; s2 += v * v;
    }
    __shared__ float red0[8][32], red1[8][32];
    __shared__ float mu_s[32], rs_s[32];
    red0[r][lane] = s; red1[r][lane] = s2;
    __syncthreads();
    if (tid < 32) {
        float a = 0.f, q = 0.f;
        #pragma unroll
        for (int i = 0; i < 8; i++) { a += red0[i][tid]; q += red1[i][tid]; }
        float mu = a * (1.f / CC);
        float var = q * (1.f / CC) - mu * mu;
        mu_s[tid] = mu;
        rs_s[tid] = rsqrtf(var + 1e-5f);
    }
    __syncthreads();

    size_t obase = ((size_t)(b * 1024 + h * 32) * TT + t) * CC;

    #pragma unroll
    for (int it = 0; it < 64; it++) {
        int e = tid + it * 256;
        int ww = e >> 9, cc = e & 511;
        float v = (tile[cc * 33 + ww] - mu_s[ww]) * rs_s[ww] * gamma[cc] + beta[cc];
        nrm[obase + (size_t)ww * (TT * CC) + cc] = f2tf_f(v);
    }
}

// ---------------------------------------------------------------------------
// K3: tensor-core attention. Block = one Bidx (8 warps = 8 heads).
//   S1 = Q@K^T (16x16), S2 = Q@Ktab^T (16x32 skew), score = S1 + gather(S2)
//   softmax -> attn (16x16) + attn2 (16x32 skew)
//   O = attn@V + attn2@Vtab   via mma.m16n8k8.tf32
// Smem strides chosen for conflict-free scalar fragment gathers:
//   A-role (Q:68, S:20, S2f:36)  -> banks 4r+c / 20r+c
//   B-role n-major (K:68, Ktab:68) -> banks 4n+k
//   B-role k-major (V:72, Vtab:72) -> banks 8k+n
// ---------------------------------------------------------------------------
#define K3_SMEM (89600)
// float offsets
#define OFF_KTAB 0                  // [32][68]
#define OFF_VTAB 2176               // [32][72]
#define OFF_BUFA 4480               // per warp 1152: Q[16][68] / S2raw[16][33] / V[16][72]
#define OFF_BUFB (4480 + 8*1152)    // per warp 1088: K[16][68] / (S[16][20] + S2f[16][36])

__global__ __launch_bounds__(256, 2) void k3_attn(const float* __restrict__ qkv,
                                                  const float* __restrict__ k_table,
                                                  const float* __restrict__ v_table,
                                                  float* __restrict__ aout) {
    extern __shared__ float sm[];
    const int tid = threadIdx.x;
    const int w = tid >> 5, lane = tid & 31;
    const int Bidx = blockIdx.x;
    const int r = lane >> 2, qc = lane & 3;

    float* ktab = sm + OFF_KTAB;
    float* vtab = sm + OFF_VTAB;
    float* bufA = sm + OFF_BUFA + w * 1152;
    float* bufB = sm + OFF_BUFB + w * 1088;

    // ---- stage tables (block-wide), rows 0..30 valid, row 31 zeroed
    #pragma unroll
    for (int it = 0; it < 8; it++) {
        int e = tid + it * 256;
        int d = e >> 6, c = e & 63;
        float kv = (d < 31) ? k_table[(49 + d) * CH + c] : 0.f;
        float vv = (d < 31) ? v_table[(49 + d) * CH + c] : 0.f;
        ktab[d * 68 + c] = f2tf_f(kv);
        vtab[d * 72 + c] = f2tf_f(vv);
    }

    // ---- stage Q, K for this warp's head
    const float* gq = qkv + (size_t)Bidx * TT * (3 * CC) + w * CH;
    #pragma unroll
    for (int it = 0; it < 8; it++) {
        int idx = lane + it * 32;
        int row = idx >> 4, c4 = (idx & 15) * 4;
        float4 vq = *(const float4*)(gq + (size_t)row * (3 * CC) + c4);
        float4 vk = *(const float4*)(gq + (size_t)row * (3 * CC) + CC + c4);
        bufA[row * 68 + c4 + 0] = f2tf_f(vq.x);
        bufA[row * 68 + c4 + 1] = f2tf_f(vq.y);
        bufA[row * 68 + c4 + 2] = f2tf_f(vq.z);
        bufA[row * 68 + c4 + 3] = f2tf_f(vq.w);
        bufB[row * 68 + c4 + 0] = f2tf_f(vk.x);
        bufB[row * 68 + c4 + 1] = f2tf_f(vk.y);
        bufB[row * 68 + c4 + 2] = f2tf_f(vk.z);
        bufB[row * 68 + c4 + 3] = f2tf_f(vk.w);
    }
    __syncthreads();

    // ---- scores: S1 (2 n-blocks over j), S2 (4 n-blocks over d)
    float c1[2][4] = {{0.f,0.f,0.f,0.f},{0.f,0.f,0.f,0.f}};
    float c2[4][4] = {{0.f,0.f,0.f,0.f},{0.f,0.f,0.f,0.f},{0.f,0.f,0.f,0.f},{0.f,0.f,0.f,0.f}};
    #pragma unroll
    for (int ks = 0; ks < 8; ks++) {
        const int k0 = ks * 8;
        uint32_t a[4];
        a[0] = __float_as_uint(bufA[r * 68 + k0 + qc]);
        a[1] = __float_as_uint(bufA[(r + 8) * 68 + k0 + qc]);
        a[2] = __float_as_uint(bufA[r * 68 + k0 + qc + 4]);
        a[3] = __float_as_uint(bufA[(r + 8) * 68 + k0 + qc + 4]);
        #pragma unroll
        for (int nb = 0; nb < 2; nb++) {
            uint32_t b0 = __float_as_uint(bufB[(nb * 8 + r) * 68 + k0 + qc]);
            uint32_t b1 = __float_as_uint(bufB[(nb * 8 + r) * 68 + k0 + qc + 4]);
            mma_tf32(c1[nb], a, b0, b1);
        }
        #pragma unroll
        for (int nb = 0; nb < 4; nb++) {
            uint32_t b0 = __float_as_uint(ktab[(nb * 8 + r) * 68 + k0 + qc]);
            uint32_t b1 = __float_as_uint(ktab[(nb * 8 + r) * 68 + k0 + qc + 4]);
            mma_tf32(c2[nb], a, b0, b1);
        }
    }
    __syncwarp();

    // ---- write S2raw [16][33] into bufA (Q dead)
    #pragma unroll
    for (int nb = 0; nb < 4; nb++) {
        #pragma unroll
        for (int q = 0; q < 4; q++) {
            int row = r + (q >> 1) * 8;
            int col = nb * 8 + 2 * qc + (q & 1);
            bufA[row * 33 + col] = c2[nb][q];
        }
    }
    // zero S/S2f region of bufB (K dead): 896 floats
    #pragma unroll
    for (int it = 0; it < 28; it++)
        bufB[lane + it * 32] = 0.f;
    __syncwarp();

    // ---- combined scores + softmax
    // value m (0..3) per row-half h: nb = m>>1, j = (m>>1)*8 + 2*qc + (m&1)
    float attv[2][4];
    #pragma unroll
    for (int h = 0; h < 2; h++) {
        int row = r + 8 * h;
        float v[4];
        #pragma unroll
        for (int m = 0; m < 4; m++) {
            int nb = m >> 1;
            int j = nb * 8 + 2 * qc + (m & 1);
            v[m] = (c1[nb][h * 2 + (m & 1)] + bufA[row * 33 + (j - row + 15)]) * 0.125f;
        }
        float mx = fmaxf(fmaxf(v[0], v[1]), fmaxf(v[2], v[3]));
        mx = fmaxf(mx, __shfl_xor_sync(0xffffffffu, mx, 1));
        mx = fmaxf(mx, __shfl_xor_sync(0xffffffffu, mx, 2));
        float sum = 0.f;
        #pragma unroll
        for (int m = 0; m < 4; m++) { v[m] = __expf(v[m] - mx); sum += v[m]; }
        sum += __shfl_xor_sync(0xffffffffu, sum, 1);
        sum += __shfl_xor_sync(0xffffffffu, sum, 2);
        float inv = 1.f / sum;
        #pragma unroll
        for (int m = 0; m < 4; m++) attv[h][m] = f2tf_f(v[m] * inv);
    }
    __syncwarp();

    // ---- scatter attn into S [16][20] and skewed S2f [16][36] (bufB)
    #pragma unroll
    for (int h = 0; h < 2; h++) {
        int row = r + 8 * h;
        #pragma unroll
        for (int m = 0; m < 4; m++) {
            int j = (m >> 1) * 8 + 2 * qc + (m & 1);
            bufB[row * 20 + j] = attv[h][m];
            bufB[320 + row * 36 + (j - row + 15)] = attv[h][m];
        }
    }

    // ---- stage V into bufA (S2raw dead)
    #pragma unroll
    for (int it = 0; it < 8; it++) {
        int idx = lane + it * 32;
        int row = idx >> 4, c4 = (idx & 15) * 4;
        float4 vv = *(const float4*)(gq + (size_t)row * (3 * CC) + 2 * CC + c4);
        bufA[row * 72 + c4 + 0] = f2tf_f(vv.x);
        bufA[row * 72 + c4 + 1] = f2tf_f(vv.y);
        bufA[row * 72 + c4 + 2] = f2tf_f(vv.z);
        bufA[row * 72 + c4 + 3] = f2tf_f(vv.w);
    }
    __syncwarp();

    // ---- output MMAs: O = attn@V + attn2@Vtab
    uint32_t aS[2][4], aS2[4][4];
    #pragma unroll
    for (int ks = 0; ks < 2; ks++) {
        aS[ks][0] = __float_as_uint(bufB[r * 20 + ks * 8 + qc]);
        aS[ks][1] = __float_as_uint(bufB[(r + 8) * 20 + ks * 8 + qc]);
        aS[ks][2] = __float_as_uint(bufB[r * 20 + ks * 8 + qc + 4]);
        aS[ks][3] = __float_as_uint(bufB[(r + 8) * 20 + ks * 8 + qc + 4]);
    }
    #pragma unroll
    for (int ks = 0; ks < 4; ks++) {
        aS2[ks][0] = __float_as_uint(bufB[320 + r * 36 + ks * 8 + qc]);
        aS2[ks][1] = __float_as_uint(bufB[320 + (r + 8) * 36 + ks * 8 + qc]);
        aS2[ks][2] = __float_as_uint(bufB[320 + r * 36 + ks * 8 + qc + 4]);
        aS2[ks][3] = __float_as_uint(bufB[320 + (r + 8) * 36 + ks * 8 + qc + 4]);
    }

    float* ga = aout + (size_t)(Bidx * TT) * CC + w * CH;
    #pragma unroll
    for (int nb = 0; nb < 8; nb++) {
        float o[4] = {0.f, 0.f, 0.f, 0.f};
        #pragma unroll
        for (int ks = 0; ks < 2; ks++) {
            uint32_t b0 = __float_as_uint(bufA[(ks * 8 + qc) * 72 + nb * 8 + r]);
            uint32_t b1 = __float_as_uint(bufA[(ks * 8 + qc + 4) * 72 + nb * 8 + r]);
            mma_tf32(o, aS[ks], b0, b1);
        }
        #pragma unroll
        for (int ks = 0; ks < 4; ks++) {
            uint32_t b0 = __float_as_uint(vtab[(ks * 8 + qc) * 72 + nb * 8 + r]);
            uint32_t b1 = __float_as_uint(vtab[(ks * 8 + qc + 4) * 72 + nb * 8 + r]);
            mma_tf32(o, aS2[ks], b0, b1);
        }
        int col = nb * 8 + 2 * qc;
        float2 v0 = make_float2(f2tf_f(o[0]), f2tf_f(o[1]));
        float2 v1 = make_float2(f2tf_f(o[2]), f2tf_f(o[3]));
        *(float2*)(ga + (size_t)r * CC + col)       = v0;
        *(float2*)(ga + (size_t)(r + 8) * CC + col) = v1;
    }
}

// ---------------------------------------------------------------------------
// K5: out = x + transpose-back(proj_seq)
// ---------------------------------------------------------------------------
__global__ __launch_bounds__(256) void k5_resid(const float* __restrict__ x,
                                                const float* __restrict__ oseq,
                                                float* __restrict__ out) {
    int bid = blockIdx.x;
    int b = bid >> 9;
    int t = (bid >> 5) & 15;
    int h = bid & 31;
    int tid = threadIdx.x;

    size_t base  = (size_t)b * (CC * TT * HH * WW) + (size_t)t * (HH * WW) + (size_t)h * WW;
    size_t obase = ((size_t)(b * 1024 + h * 32) * TT + t) * CC;

    __shared__ float tile[128 * 33];
    for (int c0 = 0; c0 < CC; c0 += 128) {
        __syncthreads();
        for (int e = tid; e < 128 * 32; e += 256) {
            int ww = e >> 7, cc = e & 127;
            tile[cc * 33 + ww] = oseq[obase + (size_t)ww * (TT * CC) + c0 + cc];
        }
        __syncthreads();
        for (int e = tid; e < 128 * 32; e += 256) {
            int cc = e >> 5, ww = e & 31;
            size_t gi = base + (size_t)(c0 + cc) * (TT*HH*WW) + ww;
            out[gi] = x[gi] + tile[cc * 33 + ww];
        }
    }
}

// ---------------------------------------------------------------------------
extern "C" void kernel_launch(void* const* d_in, const int* in_sizes, int n_in,
                              void* d_out, int out_size) {
    const float* x       = (const float*)d_in[0];
    const float* ln_g    = (const float*)d_in[1];
    const float* ln_b    = (const float*)d_in[2];
    const float* qkv_w   = (const float*)d_in[3];
    const float* qkv_b   = (const float*)d_in[4];
    const float* k_table = (const float*)d_in[5];
    const float* v_table = (const float*)d_in[6];
    const float* proj_w  = (const float*)d_in[7];
    const float* proj_b  = (const float*)d_in[8];
    float* out = (float*)d_out;

    void *p_nrm_v, *p_qkv_v, *p_att_v, *p_wq_v, *p_wp_v;
    cudaGetSymbolAddress(&p_nrm_v, g_nrm);
    cudaGetSymbolAddress(&p_qkv_v, g_qkv);
    cudaGetSymbolAddress(&p_att_v, g_att);
    cudaGetSymbolAddress(&p_wq_v, g_wq);
    cudaGetSymbolAddress(&p_wp_v, g_wp);
    float* p_nrm = (float*)p_nrm_v;
    float* p_qkv = (float*)p_qkv_v;
    float* p_att = (float*)p_att_v;
    float* p_wq  = (float*)p_wq_v;
    float* p_wp  = (float*)p_wp_v;

    cudaFuncSetAttribute(tc_gemm, cudaFuncAttributeMaxDynamicSharedMemorySize, GSMEM_SZ);
    cudaFuncSetAttribute(k1_ln, cudaFuncAttributeMaxDynamicSharedMemorySize, K1_SMEM);
    cudaFuncSetAttribute(k3_attn, cudaFuncAttributeMaxDynamicSharedMemorySize, K3_SMEM);

    wcvt<<<(3 * CC * CC + 255) / 256, 256>>>(qkv_w, proj_w, p_wq, p_wp);

    k1_ln<<<BB * TT * HH, 256, K1_SMEM>>>(x, ln_g, ln_b, p_nrm);

    {
        dim3 grid(3 * CC / 128, ROWS / 128);
        tc_gemm<<<grid, 256, GSMEM_SZ>>>(p_nrm, p_wq, qkv_b, p_qkv, ROWS, 3 * CC, CC);
    }

    k3_attn<<<BSEQ, 256, K3_SMEM>>>(p_qkv, k_table, v_table, p_att);

    {
        dim3 grid(CC / 128, ROWS / 128);
        tc_gemm<<<grid, 256, GSMEM_SZ>>>(p_att, p_wp, proj_b, p_nrm, ROWS, CC, CC);
    }

    k5_resid<<<BB * TT * HH, 256>>>(x, p_nrm, out);
}

// round 8
// speedup vs baseline: 5.2658x; 1.3317x over previous
#include <cuda_runtime.h>
#include <cuda_bf16.h>
#include <cstdint>

#define BB   2
#define CC   512
#define TT   16
#define HH   32
#define WW   32
#define NH   8
#define CH   64
#define BSEQ (BB*HH*WW)     // 2048
#define ROWS (BSEQ*TT)      // 32768

__device__ __nv_bfloat16 g_act[(size_t)ROWS * CC];       // LN output (bf16)
__device__ float         g_qkv[(size_t)ROWS * 3 * CC];   // qkv output (fp32)
__device__ __nv_bfloat16 g_attb[(size_t)ROWS * CC];      // attention output (bf16)
__device__ float         g_proj[(size_t)ROWS * CC];      // proj output (fp32)
__device__ __nv_bfloat16 g_wq[(size_t)3 * CC * CC];
__device__ __nv_bfloat16 g_wp[(size_t)CC * CC];

// ---------------------------------------------------------------------------
__device__ __forceinline__ uint32_t smem_u32(const void* p) {
    uint32_t a;
    asm("{ .reg .u64 t; cvta.to.shared.u64 t, %1; cvt.u32.u64 %0, t; }" : "=r"(a) : "l"(p));
    return a;
}
#define SWZ(o) ((o) ^ ((((uint32_t)(o)) >> 3) & 0x70))

__device__ __forceinline__ void cpasync16(uint32_t dst, const void* src) {
    asm volatile("cp.async.cg.shared.global [%0], [%1], 16;" :: "r"(dst), "l"(src));
}
__device__ __forceinline__ void ldsm_x4(uint32_t* r, uint32_t addr) {
    asm volatile("ldmatrix.sync.aligned.m8n8.x4.shared.b16 {%0,%1,%2,%3}, [%4];"
                 : "=r"(r[0]), "=r"(r[1]), "=r"(r[2]), "=r"(r[3]) : "r"(addr));
}
__device__ __forceinline__ float f2tf_f(float x) {
    uint32_t y;
    asm("cvt.rna.tf32.f32 %0, %1;" : "=r"(y) : "r"(__float_as_uint(x)));
    return __uint_as_float(y);
}
__device__ __forceinline__ void mma_tf32(float* c, const uint32_t* a, uint32_t b0, uint32_t b1) {
    asm volatile(
        "mma.sync.aligned.m16n8k8.row.col.f32.tf32.tf32.f32 "
        "{%0,%1,%2,%3}, {%4,%5,%6,%7}, {%8,%9}, {%0,%1,%2,%3};"
        : "+f"(c[0]), "+f"(c[1]), "+f"(c[2]), "+f"(c[3])
        : "r"(a[0]), "r"(a[1]), "r"(a[2]), "r"(a[3]), "r"(b0), "r"(b1));
}
__device__ __forceinline__ void mma_bf16(float* c, const uint32_t* a, uint32_t b0, uint32_t b1) {
    asm volatile(
        "mma.sync.aligned.m16n8k16.row.col.f32.bf16.bf16.f32 "
        "{%0,%1,%2,%3}, {%4,%5,%6,%7}, {%8,%9}, {%0,%1,%2,%3};"
        : "+f"(c[0]), "+f"(c[1]), "+f"(c[2]), "+f"(c[3])
        : "r"(a[0]), "r"(a[1]), "r"(a[2]), "r"(a[3]), "r"(b0), "r"(b1));
}

// ---------------------------------------------------------------------------
// Weight pre-convert to bf16
// ---------------------------------------------------------------------------
__global__ __launch_bounds__(256) void wcvt(const float* __restrict__ qkv_w,
                                            const float* __restrict__ proj_w,
                                            __nv_bfloat16* __restrict__ wq,
                                            __nv_bfloat16* __restrict__ wp) {
    int i = blockIdx.x * 256 + threadIdx.x;
    if (i < 3 * CC * CC) wq[i] = __float2bfloat16_rn(qkv_w[i]);
    if (i < CC * CC)     wp[i] = __float2bfloat16_rn(proj_w[i]);
}

// ---------------------------------------------------------------------------
// BF16 tensor GEMM-NT: C[M,N] = A[M,K] @ W[N,K]^T + bias (fp32 accum/out)
// CTA 128x128, BK=64 (128B rows), 8 warps (64x32 each), 3-stage cp.async.
// ---------------------------------------------------------------------------
#define NSTAGE   3
#define STAGE_SZ 32768               // A 16KB + B 16KB (bf16, 128 rows x 128B)
#define GSMEM_SZ (NSTAGE*STAGE_SZ)

__global__ __launch_bounds__(256, 2) void tc_gemm(const __nv_bfloat16* __restrict__ A,
                                                  const __nv_bfloat16* __restrict__ W,
                                                  const float* __restrict__ bias,
                                                  float* __restrict__ C,
                                                  int M, int N, int K) {
    extern __shared__ __align__(1024) char smraw[];
    const uint32_t base = smem_u32(smraw);

    const int tid  = threadIdx.x;
    const int wid  = tid >> 5, lane = tid & 31;
    const int wm   = wid & 1, wn = wid >> 1;
    const int bn   = blockIdx.x, bm = blockIdx.y;
    const int nch  = K >> 6;                        // BK=64 elements

    // cp.async per-thread precompute: 1024 16B ops each for A and B
    uint32_t st_off[4];
    const __nv_bfloat16* ga[4];
    const __nv_bfloat16* gw[4];
    #pragma unroll
    for (int it = 0; it < 4; it++) {
        int idx = tid + it * 256;
        int r = idx >> 3, c16 = idx & 7;             // row, 16B unit (8 bf16)
        st_off[it] = SWZ((uint32_t)(r * 128 + c16 * 16));
        ga[it] = A + (size_t)(bm * 128 + r) * K + c16 * 8;
        gw[it] = W + (size_t)(bn * 128 + r) * K + c16 * 8;
    }

    auto load_chunk = [&](int l) {
        const int k0 = l << 6;
        const uint32_t sA = base + (l % NSTAGE) * STAGE_SZ;
        const uint32_t sB = sA + 16384;
        #pragma unroll
        for (int it = 0; it < 4; it++) {
            cpasync16(sA + st_off[it], ga[it] + k0);
            cpasync16(sB + st_off[it], gw[it] + k0);
        }
        asm volatile("cp.async.commit_group;" ::: "memory");
    };

    load_chunk(0);
    load_chunk(1);

    // ldmatrix base offsets (ks=0): row = group row, byteoff = (lane>>4)*16
    const int m_row_in = ((lane >> 3) & 1) * 8 + (lane & 7);
    const int m_kb     = (lane >> 4) * 16;
    uint32_t a_off[4], b_off[2];
    #pragma unroll
    for (int f = 0; f < 4; f++) {
        int row = wm * 64 + f * 16 + m_row_in;
        a_off[f] = (uint32_t)(row * 128 + (m_kb ^ ((row & 7) << 4)));
    }
    #pragma unroll
    for (int p = 0; p < 2; p++) {
        int row = wn * 32 + p * 16 + m_row_in;
        b_off[p] = (uint32_t)(row * 128 + (m_kb ^ ((row & 7) << 4)));
    }

    float acc[4][4][4];
    #pragma unroll
    for (int f = 0; f < 4; f++)
        #pragma unroll
        for (int g = 0; g < 4; g++)
            #pragma unroll
            for (int r = 0; r < 4; r++) acc[f][g][r] = 0.f;

    for (int c = 0; c < nch; c++) {
        asm volatile("cp.async.wait_group 1;" ::: "memory");
        __syncthreads();

        if (c + 2 < nch) load_chunk(c + 2);

        const uint32_t sA = base + (c % NSTAGE) * STAGE_SZ;
        const uint32_t sB = sA + 16384;

        #pragma unroll
        for (int ks = 0; ks < 4; ks++) {             // k16 steps within BK=64
            uint32_t a[4][4], b[2][4];
            #pragma unroll
            for (int f = 0; f < 4; f++)
                ldsm_x4(a[f], sA + (a_off[f] ^ (ks << 5)));
            #pragma unroll
            for (int p = 0; p < 2; p++)
                ldsm_x4(b[p], sB + (b_off[p] ^ (ks << 5)));

            // n-block g: b regs {b[g>>1][g&1], b[g>>1][(g&1)+2]}
            #pragma unroll
            for (int f = 0; f < 4; f++)
                #pragma unroll
                for (int g = 0; g < 4; g++)
                    mma_bf16(acc[f][g], a[f], b[g >> 1][g & 1], b[g >> 1][(g & 1) + 2]);
        }
        __syncthreads();
    }

    const int col_in = 2 * (lane & 3);
    #pragma unroll
    for (int g = 0; g < 4; g++) {
        const int col = bn * 128 + wn * 32 + g * 8 + col_in;
        const float b0 = bias[col], b1 = bias[col + 1];
        #pragma unroll
        for (int f = 0; f < 4; f++) {
            const size_t r0 = (size_t)bm * 128 + wm * 64 + f * 16 + (lane >> 2);
            float2 v0 = make_float2(acc[f][g][0] + b0, acc[f][g][1] + b1);
            float2 v1 = make_float2(acc[f][g][2] + b0, acc[f][g][3] + b1);
            *(float2*)(C + r0 * N + col)       = v0;
            *(float2*)(C + (r0 + 8) * N + col) = v1;
        }
    }
}

// ---------------------------------------------------------------------------
// K1: (b,c,t,h,w) -> LayerNorm over c -> bf16 g_act[(b*1024+h*32+w)*16+t][c]
// ---------------------------------------------------------------------------
#define K1_SMEM (512 * 33 * 4)

__global__ __launch_bounds__(256) void k1_ln(const float* __restrict__ x,
                                             const float* __restrict__ gamma,
                                             const float* __restrict__ beta,
                                             __nv_bfloat16* __restrict__ nrm) {
    extern __shared__ float tile[];
    int bid = blockIdx.x;
    int b = bid >> 9;
    int t = (bid >> 5) & 15;
    int h = bid & 31;
    int tid = threadIdx.x;
    int lane = tid & 31, r = tid >> 5;

    size_t xbase = (size_t)b * (CC * TT * HH * WW) + (size_t)t * (HH * WW) + (size_t)h * WW;

    #pragma unroll
    for (int it = 0; it < 64; it++) {
        int e = tid + it * 256;
        int cc = e >> 5, ww = e & 31;
        tile[cc * 33 + ww] = x[xbase + (size_t)cc * (TT*HH*WW) + ww];
    }
    __syncthreads();

    float s = 0.f, s2 = 0.f;
    for (int cc = r; cc < CC; cc += 8) {
        float v = tile[cc * 33 + lane];
        s += v; s2 += v * v;
    }
    __shared__ float red0[8][32], red1[8][32];
    __shared__ float mu_s[32], rs_s[32];
    red0[r][lane] = s; red1[r][lane] = s2;
    __syncthreads();
    if (tid < 32) {
        float a = 0.f, q = 0.f;
        #pragma unroll
        for (int i = 0; i < 8; i++) { a += red0[i][tid]; q += red1[i][tid]; }
        float mu = a * (1.f / CC);
        float var = q * (1.f / CC) - mu * mu;
        mu_s[tid] = mu;
        rs_s[tid] = rsqrtf(var + 1e-5f);
    }
    __syncthreads();

    size_t obase = ((size_t)(b * 1024 + h * 32) * TT + t) * CC;

    #pragma unroll
    for (int it = 0; it < 64; it++) {
        int e = tid + it * 256;
        int ww = e >> 9, cc = e & 511;
        float v = (tile[cc * 33 + ww] - mu_s[ww]) * rs_s[ww] * gamma[cc] + beta[cc];
        nrm[obase + (size_t)ww * (TT * CC) + cc] = __float2bfloat16_rn(v);
    }
}

// ---------------------------------------------------------------------------
// K3: tensor-core attention (tf32 internals), bf16 output.
// ---------------------------------------------------------------------------
#define K3_SMEM (89600)
#define OFF_KTAB 0
#define OFF_VTAB 2176
#define OFF_BUFA 4480
#define OFF_BUFB (4480 + 8*1152)

__global__ __launch_bounds__(256, 2) void k3_attn(const float* __restrict__ qkv,
                                                  const float* __restrict__ k_table,
                                                  const float* __restrict__ v_table,
                                                  __nv_bfloat16* __restrict__ aout) {
    extern __shared__ float sm[];
    const int tid = threadIdx.x;
    const int w = tid >> 5, lane = tid & 31;
    const int Bidx = blockIdx.x;
    const int r = lane >> 2, qc = lane & 3;

    float* ktab = sm + OFF_KTAB;
    float* vtab = sm + OFF_VTAB;
    float* bufA = sm + OFF_BUFA + w * 1152;
    float* bufB = sm + OFF_BUFB + w * 1088;

    #pragma unroll
    for (int it = 0; it < 8; it++) {
        int e = tid + it * 256;
        int d = e >> 6, c = e & 63;
        float kv = (d < 31) ? k_table[(49 + d) * CH + c] : 0.f;
        float vv = (d < 31) ? v_table[(49 + d) * CH + c] : 0.f;
        ktab[d * 68 + c] = f2tf_f(kv);
        vtab[d * 72 + c] = f2tf_f(vv);
    }

    const float* gq = qkv + (size_t)Bidx * TT * (3 * CC) + w * CH;
    #pragma unroll
    for (int it = 0; it < 8; it++) {
        int idx = lane + it * 32;
        int row = idx >> 4, c4 = (idx & 15) * 4;
        float4 vq = *(const float4*)(gq + (size_t)row * (3 * CC) + c4);
        float4 vk = *(const float4*)(gq + (size_t)row * (3 * CC) + CC + c4);
        bufA[row * 68 + c4 + 0] = f2tf_f(vq.x);
        bufA[row * 68 + c4 + 1] = f2tf_f(vq.y);
        bufA[row * 68 + c4 + 2] = f2tf_f(vq.z);
        bufA[row * 68 + c4 + 3] = f2tf_f(vq.w);
        bufB[row * 68 + c4 + 0] = f2tf_f(vk.x);
        bufB[row * 68 + c4 + 1] = f2tf_f(vk.y);
        bufB[row * 68 + c4 + 2] = f2tf_f(vk.z);
        bufB[row * 68 + c4 + 3] = f2tf_f(vk.w);
    }
    __syncthreads();

    float c1[2][4] = {{0.f,0.f,0.f,0.f},{0.f,0.f,0.f,0.f}};
    float c2[4][4] = {{0.f,0.f,0.f,0.f},{0.f,0.f,0.f,0.f},{0.f,0.f,0.f,0.f},{0.f,0.f,0.f,0.f}};
    #pragma unroll
    for (int ks = 0; ks < 8; ks++) {
        const int k0 = ks * 8;
        uint32_t a[4];
        a[0] = __float_as_uint(bufA[r * 68 + k0 + qc]);
        a[1] = __float_as_uint(bufA[(r + 8) * 68 + k0 + qc]);
        a[2] = __float_as_uint(bufA[r * 68 + k0 + qc + 4]);
        a[3] = __float_as_uint(bufA[(r + 8) * 68 + k0 + qc + 4]);
        #pragma unroll
        for (int nb = 0; nb < 2; nb++) {
            uint32_t b0 = __float_as_uint(bufB[(nb * 8 + r) * 68 + k0 + qc]);
            uint32_t b1 = __float_as_uint(bufB[(nb * 8 + r) * 68 + k0 + qc + 4]);
            mma_tf32(c1[nb], a, b0, b1);
        }
        #pragma unroll
        for (int nb = 0; nb < 4; nb++) {
            uint32_t b0 = __float_as_uint(ktab[(nb * 8 + r) * 68 + k0 + qc]);
            uint32_t b1 = __float_as_uint(ktab[(nb * 8 + r) * 68 + k0 + qc + 4]);
            mma_tf32(c2[nb], a, b0, b1);
        }
    }
    __syncwarp();

    #pragma unroll
    for (int nb = 0; nb < 4; nb++) {
        #pragma unroll
        for (int q = 0; q < 4; q++) {
            int row = r + (q >> 1) * 8;
            int col = nb * 8 + 2 * qc + (q & 1);
            bufA[row * 33 + col] = c2[nb][q];
        }
    }
    #pragma unroll
    for (int it = 0; it < 28; it++)
        bufB[lane + it * 32] = 0.f;
    __syncwarp();

    float attv[2][4];
    #pragma unroll
    for (int h = 0; h < 2; h++) {
        int row = r + 8 * h;
        float v[4];
        #pragma unroll
        for (int m = 0; m < 4; m++) {
            int nb = m >> 1;
            int j = nb * 8 + 2 * qc + (m & 1);
            v[m] = (c1[nb][h * 2 + (m & 1)] + bufA[row * 33 + (j - row + 15)]) * 0.125f;
        }
        float mx = fmaxf(fmaxf(v[0], v[1]), fmaxf(v[2], v[3]));
        mx = fmaxf(mx, __shfl_xor_sync(0xffffffffu, mx, 1));
        mx = fmaxf(mx, __shfl_xor_sync(0xffffffffu, mx, 2));
        float sum = 0.f;
        #pragma unroll
        for (int m = 0; m < 4; m++) { v[m] = __expf(v[m] - mx); sum += v[m]; }
        sum += __shfl_xor_sync(0xffffffffu, sum, 1);
        sum += __shfl_xor_sync(0xffffffffu, sum, 2);
        float inv = 1.f / sum;
        #pragma unroll
        for (int m = 0; m < 4; m++) attv[h][m] = f2tf_f(v[m] * inv);
    }
    __syncwarp();

    #pragma unroll
    for (int h = 0; h < 2; h++) {
        int row = r + 8 * h;
        #pragma unroll
        for (int m = 0; m < 4; m++) {
            int j = (m >> 1) * 8 + 2 * qc + (m & 1);
            bufB[row * 20 + j] = attv[h][m];
            bufB[320 + row * 36 + (j - row + 15)] = attv[h][m];
        }
    }

    #pragma unroll
    for (int it = 0; it < 8; it++) {
        int idx = lane + it * 32;
        int row = idx >> 4, c4 = (idx & 15) * 4;
        float4 vv = *(const float4*)(gq + (size_t)row * (3 * CC) + 2 * CC + c4);
        bufA[row * 72 + c4 + 0] = f2tf_f(vv.x);
        bufA[row * 72 + c4 + 1] = f2tf_f(vv.y);
        bufA[row * 72 + c4 + 2] = f2tf_f(vv.z);
        bufA[row * 72 + c4 + 3] = f2tf_f(vv.w);
    }
    __syncwarp();

    uint32_t aS[2][4], aS2[4][4];
    #pragma unroll
    for (int ks = 0; ks < 2; ks++) {
        aS[ks][0] = __float_as_uint(bufB[r * 20 + ks * 8 + qc]);
        aS[ks][1] = __float_as_uint(bufB[(r + 8) * 20 + ks * 8 + qc]);
        aS[ks][2] = __float_as_uint(bufB[r * 20 + ks * 8 + qc + 4]);
        aS[ks][3] = __float_as_uint(bufB[(r + 8) * 20 + ks * 8 + qc + 4]);
    }
    #pragma unroll
    for (int ks = 0; ks < 4; ks++) {
        aS2[ks][0] = __float_as_uint(bufB[320 + r * 36 + ks * 8 + qc]);
        aS2[ks][1] = __float_as_uint(bufB[320 + (r + 8) * 36 + ks * 8 + qc]);
        aS2[ks][2] = __float_as_uint(bufB[320 + r * 36 + ks * 8 + qc + 4]);
        aS2[ks][3] = __float_as_uint(bufB[320 + (r + 8) * 36 + ks * 8 + qc + 4]);
    }

    __nv_bfloat16* ga = aout + (size_t)(Bidx * TT) * CC + w * CH;
    #pragma unroll
    for (int nb = 0; nb < 8; nb++) {
        float o[4] = {0.f, 0.f, 0.f, 0.f};
        #pragma unroll
        for (int ks = 0; ks < 2; ks++) {
            uint32_t b0 = __float_as_uint(bufA[(ks * 8 + qc) * 72 + nb * 8 + r]);
            uint32_t b1 = __float_as_uint(bufA[(ks * 8 + qc + 4) * 72 + nb * 8 + r]);
            mma_tf32(o, aS[ks], b0, b1);
        }
        #pragma unroll
        for (int ks = 0; ks < 4; ks++) {
            uint32_t b0 = __float_as_uint(vtab[(ks * 8 + qc) * 72 + nb * 8 + r]);
            uint32_t b1 = __float_as_uint(vtab[(ks * 8 + qc + 4) * 72 + nb * 8 + r]);
            mma_tf32(o, aS2[ks], b0, b1);
        }
        int col = nb * 8 + 2 * qc;
        __nv_bfloat162 p0, p1;
        p0.x = __float2bfloat16_rn(o[0]); p0.y = __float2bfloat16_rn(o[1]);
        p1.x = __float2bfloat16_rn(o[2]); p1.y = __float2bfloat16_rn(o[3]);
        *(__nv_bfloat162*)(ga + (size_t)r * CC + col)       = p0;
        *(__nv_bfloat162*)(ga + (size_t)(r + 8) * CC + col) = p1;
    }
}

// ---------------------------------------------------------------------------
// K5: out = x + transpose-back(proj_seq)
// ---------------------------------------------------------------------------
__global__ __launch_bounds__(256) void k5_resid(const float* __restrict__ x,
                                                const float* __restrict__ oseq,
                                                float* __restrict__ out) {
    int bid = blockIdx.x;
    int b = bid >> 9;
    int t = (bid >> 5) & 15;
    int h = bid & 31;
    int tid = threadIdx.x;

    size_t base  = (size_t)b * (CC * TT * HH * WW) + (size_t)t * (HH * WW) + (size_t)h * WW;
    size_t obase = ((size_t)(b * 1024 + h * 32) * TT + t) * CC;

    __shared__ float tile[128 * 33];
    for (int c0 = 0; c0 < CC; c0 += 128) {
        __syncthreads();
        for (int e = tid; e < 128 * 32; e += 256) {
            int ww = e >> 7, cc = e & 127;
            tile[cc * 33 + ww] = oseq[obase + (size_t)ww * (TT * CC) + c0 + cc];
        }
        __syncthreads();
        for (int e = tid; e < 128 * 32; e += 256) {
            int cc = e >> 5, ww = e & 31;
            size_t gi = base + (size_t)(c0 + cc) * (TT*HH*WW) + ww;
            out[gi] = x[gi] + tile[cc * 33 + ww];
        }
    }
}

// ---------------------------------------------------------------------------
extern "C" void kernel_launch(void* const* d_in, const int* in_sizes, int n_in,
                              void* d_out, int out_size) {
    const float* x       = (const float*)d_in[0];
    const float* ln_g    = (const float*)d_in[1];
    const float* ln_b    = (const float*)d_in[2];
    const float* qkv_w   = (const float*)d_in[3];
    const float* qkv_b   = (const float*)d_in[4];
    const float* k_table = (const float*)d_in[5];
    const float* v_table = (const float*)d_in[6];
    const float* proj_w  = (const float*)d_in[7];
    const float* proj_b  = (const float*)d_in[8];
    float* out = (float*)d_out;

    void *p_act_v, *p_qkv_v, *p_attb_v, *p_proj_v, *p_wq_v, *p_wp_v;
    cudaGetSymbolAddress(&p_act_v, g_act);
    cudaGetSymbolAddress(&p_qkv_v, g_qkv);
    cudaGetSymbolAddress(&p_attb_v, g_attb);
    cudaGetSymbolAddress(&p_proj_v, g_proj);
    cudaGetSymbolAddress(&p_wq_v, g_wq);
    cudaGetSymbolAddress(&p_wp_v, g_wp);
    __nv_bfloat16* p_act  = (__nv_bfloat16*)p_act_v;
    float*         p_qkv  = (float*)p_qkv_v;
    __nv_bfloat16* p_attb = (__nv_bfloat16*)p_attb_v;
    float*         p_proj = (float*)p_proj_v;
    __nv_bfloat16* p_wq   = (__nv_bfloat16*)p_wq_v;
    __nv_bfloat16* p_wp   = (__nv_bfloat16*)p_wp_v;

    cudaFuncSetAttribute(tc_gemm, cudaFuncAttributeMaxDynamicSharedMemorySize, GSMEM_SZ);
    cudaFuncSetAttribute(k1_ln, cudaFuncAttributeMaxDynamicSharedMemorySize, K1_SMEM);
    cudaFuncSetAttribute(k3_attn, cudaFuncAttributeMaxDynamicSharedMemorySize, K3_SMEM);

    wcvt<<<(3 * CC * CC + 255) / 256, 256>>>(qkv_w, proj_w, p_wq, p_wp);

    k1_ln<<<BB * TT * HH, 256, K1_SMEM>>>(x, ln_g, ln_b, p_act);

    {
        dim3 grid(3 * CC / 128, ROWS / 128);
        tc_gemm<<<grid, 256, GSMEM_SZ>>>(p_act, p_wq, qkv_b, p_qkv, ROWS, 3 * CC, CC);
    }

    k3_attn<<<BSEQ, 256, K3_SMEM>>>(p_qkv, k_table, v_table, p_attb);

    {
        dim3 grid(CC / 128, ROWS / 128);
        tc_gemm<<<grid, 256, GSMEM_SZ>>>(p_attb, p_wp, proj_b, p_proj, ROWS, CC, CC);
    }

    k5_resid<<<BB * TT * HH, 256>>>(x, p_proj, out);
}

// round 9
// speedup vs baseline: 5.3535x; 1.0167x over previous
#include <cuda_runtime.h>
#include <cuda_bf16.h>
#include <cstdint>

#define BB   2
#define CC   512
#define TT   16
#define HH   32
#define WW   32
#define NH   8
#define CH   64
#define BSEQ (BB*HH*WW)     // 2048
#define ROWS (BSEQ*TT)      // 32768

__device__ __nv_bfloat16 g_act[(size_t)ROWS * CC];       // LN output (bf16)
__device__ __nv_bfloat16 g_qkv[(size_t)ROWS * 3 * CC];   // qkv output (bf16)
__device__ __nv_bfloat16 g_attb[(size_t)ROWS * CC];      // attention output (bf16)
__device__ __nv_bfloat16 g_proj[(size_t)ROWS * CC];      // proj output (bf16)
__device__ __nv_bfloat16 g_wq[(size_t)3 * CC * CC];
__device__ __nv_bfloat16 g_wp[(size_t)CC * CC];

// ---------------------------------------------------------------------------
__device__ __forceinline__ uint32_t smem_u32(const void* p) {
    uint32_t a;
    asm("{ .reg .u64 t; cvta.to.shared.u64 t, %1; cvt.u32.u64 %0, t; }" : "=r"(a) : "l"(p));
    return a;
}
#define SWZ(o) ((o) ^ ((((uint32_t)(o)) >> 3) & 0x70))

__device__ __forceinline__ void cpasync16(uint32_t dst, const void* src) {
    asm volatile("cp.async.cg.shared.global [%0], [%1], 16;" :: "r"(dst), "l"(src));
}
__device__ __forceinline__ void ldsm_x4(uint32_t* r, uint32_t addr) {
    asm volatile("ldmatrix.sync.aligned.m8n8.x4.shared.b16 {%0,%1,%2,%3}, [%4];"
                 : "=r"(r[0]), "=r"(r[1]), "=r"(r[2]), "=r"(r[3]) : "r"(addr));
}
__device__ __forceinline__ float f2tf_f(float x) {
    uint32_t y;
    asm("cvt.rna.tf32.f32 %0, %1;" : "=r"(y) : "r"(__float_as_uint(x)));
    return __uint_as_float(y);
}
__device__ __forceinline__ void mma_tf32(float* c, const uint32_t* a, uint32_t b0, uint32_t b1) {
    asm volatile(
        "mma.sync.aligned.m16n8k8.row.col.f32.tf32.tf32.f32 "
        "{%0,%1,%2,%3}, {%4,%5,%6,%7}, {%8,%9}, {%0,%1,%2,%3};"
        : "+f"(c[0]), "+f"(c[1]), "+f"(c[2]), "+f"(c[3])
        : "r"(a[0]), "r"(a[1]), "r"(a[2]), "r"(a[3]), "r"(b0), "r"(b1));
}
__device__ __forceinline__ void mma_bf16(float* c, const uint32_t* a, uint32_t b0, uint32_t b1) {
    asm volatile(
        "mma.sync.aligned.m16n8k16.row.col.f32.bf16.bf16.f32 "
        "{%0,%1,%2,%3}, {%4,%5,%6,%7}, {%8,%9}, {%0,%1,%2,%3};"
        : "+f"(c[0]), "+f"(c[1]), "+f"(c[2]), "+f"(c[3])
        : "r"(a[0]), "r"(a[1]), "r"(a[2]), "r"(a[3]), "r"(b0), "r"(b1));
}

// ---------------------------------------------------------------------------
__global__ __launch_bounds__(256) void wcvt(const float* __restrict__ qkv_w,
                                            const float* __restrict__ proj_w,
                                            __nv_bfloat16* __restrict__ wq,
                                            __nv_bfloat16* __restrict__ wp) {
    int i = blockIdx.x * 256 + threadIdx.x;
    if (i < 3 * CC * CC) wq[i] = __float2bfloat16_rn(qkv_w[i]);
    if (i < CC * CC)     wp[i] = __float2bfloat16_rn(proj_w[i]);
}

// ---------------------------------------------------------------------------
// BF16 tensor GEMM-NT: C[M,N] = A[M,K] @ W[N,K]^T + bias, bf16 out, fp32 accum
// CTA 128x128, BK=64, 8 warps (64x32 each), 3-stage cp.async.
// ---------------------------------------------------------------------------
#define NSTAGE   3
#define STAGE_SZ 32768
#define GSMEM_SZ (NSTAGE*STAGE_SZ)

__global__ __launch_bounds__(256, 2) void tc_gemm(const __nv_bfloat16* __restrict__ A,
                                                  const __nv_bfloat16* __restrict__ W,
                                                  const float* __restrict__ bias,
                                                  __nv_bfloat16* __restrict__ C,
                                                  int M, int N, int K) {
    extern __shared__ __align__(1024) char smraw[];
    const uint32_t base = smem_u32(smraw);

    const int tid  = threadIdx.x;
    const int wid  = tid >> 5, lane = tid & 31;
    const int wm   = wid & 1, wn = wid >> 1;
    const int bn   = blockIdx.x, bm = blockIdx.y;
    const int nch  = K >> 6;

    uint32_t st_off[4];
    const __nv_bfloat16* ga[4];
    const __nv_bfloat16* gw[4];
    #pragma unroll
    for (int it = 0; it < 4; it++) {
        int idx = tid + it * 256;
        int r = idx >> 3, c16 = idx & 7;
        st_off[it] = SWZ((uint32_t)(r * 128 + c16 * 16));
        ga[it] = A + (size_t)(bm * 128 + r) * K + c16 * 8;
        gw[it] = W + (size_t)(bn * 128 + r) * K + c16 * 8;
    }

    auto load_chunk = [&](int l) {
        const int k0 = l << 6;
        const uint32_t sA = base + (l % NSTAGE) * STAGE_SZ;
        const uint32_t sB = sA + 16384;
        #pragma unroll
        for (int it = 0; it < 4; it++) {
            cpasync16(sA + st_off[it], ga[it] + k0);
            cpasync16(sB + st_off[it], gw[it] + k0);
        }
        asm volatile("cp.async.commit_group;" ::: "memory");
    };

    load_chunk(0);
    load_chunk(1);

    const int m_row_in = ((lane >> 3) & 1) * 8 + (lane & 7);
    const int m_kb     = (lane >> 4) * 16;
    uint32_t a_off[4], b_off[2];
    #pragma unroll
    for (int f = 0; f < 4; f++) {
        int row = wm * 64 + f * 16 + m_row_in;
        a_off[f] = (uint32_t)(row * 128 + (m_kb ^ ((row & 7) << 4)));
    }
    #pragma unroll
    for (int p = 0; p < 2; p++) {
        int row = wn * 32 + p * 16 + m_row_in;
        b_off[p] = (uint32_t)(row * 128 + (m_kb ^ ((row & 7) << 4)));
    }

    float acc[4][4][4];
    #pragma unroll
    for (int f = 0; f < 4; f++)
        #pragma unroll
        for (int g = 0; g < 4; g++)
            #pragma unroll
            for (int r = 0; r < 4; r++) acc[f][g][r] = 0.f;

    for (int c = 0; c < nch; c++) {
        asm volatile("cp.async.wait_group 1;" ::: "memory");
        __syncthreads();

        if (c + 2 < nch) load_chunk(c + 2);

        const uint32_t sA = base + (c % NSTAGE) * STAGE_SZ;
        const uint32_t sB = sA + 16384;

        #pragma unroll
        for (int ks = 0; ks < 4; ks++) {
            uint32_t a[4][4], b[2][4];
            #pragma unroll
            for (int f = 0; f < 4; f++)
                ldsm_x4(a[f], sA + (a_off[f] ^ (ks << 5)));
            #pragma unroll
            for (int p = 0; p < 2; p++)
                ldsm_x4(b[p], sB + (b_off[p] ^ (ks << 5)));

            #pragma unroll
            for (int f = 0; f < 4; f++)
                #pragma unroll
                for (int g = 0; g < 4; g++)
                    mma_bf16(acc[f][g], a[f], b[g >> 1][g & 1], b[g >> 1][(g & 1) + 2]);
        }
        __syncthreads();
    }

    const int col_in = 2 * (lane & 3);
    #pragma unroll
    for (int g = 0; g < 4; g++) {
        const int col = bn * 128 + wn * 32 + g * 8 + col_in;
        const float b0 = bias[col], b1 = bias[col + 1];
        #pragma unroll
        for (int f = 0; f < 4; f++) {
            const size_t r0 = (size_t)bm * 128 + wm * 64 + f * 16 + (lane >> 2);
            __nv_bfloat162 p0, p1;
            p0.x = __float2bfloat16_rn(acc[f][g][0] + b0);
            p0.y = __float2bfloat16_rn(acc[f][g][1] + b1);
            p1.x = __float2bfloat16_rn(acc[f][g][2] + b0);
            p1.y = __float2bfloat16_rn(acc[f][g][3] + b1);
            *(__nv_bfloat162*)(C + r0 * N + col)       = p0;
            *(__nv_bfloat162*)(C + (r0 + 8) * N + col) = p1;
        }
    }
}

// ---------------------------------------------------------------------------
// K1: (b,c,t,h,w) -> LayerNorm over c -> bf16 g_act
// ---------------------------------------------------------------------------
#define K1_SMEM (512 * 33 * 4)

__global__ __launch_bounds__(256) void k1_ln(const float* __restrict__ x,
                                             const float* __restrict__ gamma,
                                             const float* __restrict__ beta,
                                             __nv_bfloat16* __restrict__ nrm) {
    extern __shared__ float tile[];
    int bid = blockIdx.x;
    int b = bid >> 9;
    int t = (bid >> 5) & 15;
    int h = bid & 31;
    int tid = threadIdx.x;
    int lane = tid & 31, r = tid >> 5;

    size_t xbase = (size_t)b * (CC * TT * HH * WW) + (size_t)t * (HH * WW) + (size_t)h * WW;

    #pragma unroll
    for (int it = 0; it < 64; it++) {
        int e = tid + it * 256;
        int cc = e >> 5, ww = e & 31;
        tile[cc * 33 + ww] = x[xbase + (size_t)cc * (TT*HH*WW) + ww];
    }
    __syncthreads();

    float s = 0.f, s2 = 0.f;
    for (int cc = r; cc < CC; cc += 8) {
        float v = tile[cc * 33 + lane];
        s += v; s2 += v * v;
    }
    __shared__ float red0[8][32], red1[8][32];
    __shared__ float mu_s[32], rs_s[32];
    red0[r][lane] = s; red1[r][lane] = s2;
    __syncthreads();
    if (tid < 32) {
        float a = 0.f, q = 0.f;
        #pragma unroll
        for (int i = 0; i < 8; i++) { a += red0[i][tid]; q += red1[i][tid]; }
        float mu = a * (1.f / CC);
        float var = q * (1.f / CC) - mu * mu;
        mu_s[tid] = mu;
        rs_s[tid] = rsqrtf(var + 1e-5f);
    }
    __syncthreads();

    size_t obase = ((size_t)(b * 1024 + h * 32) * TT + t) * CC;

    #pragma unroll
    for (int it = 0; it < 64; it++) {
        int e = tid + it * 256;
        int ww = e >> 9, cc = e & 511;
        float v = (tile[cc * 33 + ww] - mu_s[ww]) * rs_s[ww] * gamma[cc] + beta[cc];
        nrm[obase + (size_t)ww * (TT * CC) + cc] = __float2bfloat16_rn(v);
    }
}

// ---------------------------------------------------------------------------
// K3: tensor-core attention; qkv input bf16, output bf16, tf32 internals.
// ---------------------------------------------------------------------------
#define K3_SMEM (89600)
#define OFF_KTAB 0
#define OFF_VTAB 2176
#define OFF_BUFA 4480
#define OFF_BUFB (4480 + 8*1152)

__global__ __launch_bounds__(256, 2) void k3_attn(const __nv_bfloat16* __restrict__ qkv,
                                                  const float* __restrict__ k_table,
                                                  const float* __restrict__ v_table,
                                                  __nv_bfloat16* __restrict__ aout) {
    extern __shared__ float sm[];
    const int tid = threadIdx.x;
    const int w = tid >> 5, lane = tid & 31;
    const int Bidx = blockIdx.x;
    const int r = lane >> 2, qc = lane & 3;

    float* ktab = sm + OFF_KTAB;
    float* vtab = sm + OFF_VTAB;
    float* bufA = sm + OFF_BUFA + w * 1152;
    float* bufB = sm + OFF_BUFB + w * 1088;

    #pragma unroll
    for (int it = 0; it < 8; it++) {
        int e = tid + it * 256;
        int d = e >> 6, c = e & 63;
        float kv = (d < 31) ? k_table[(49 + d) * CH + c] : 0.f;
        float vv = (d < 31) ? v_table[(49 + d) * CH + c] : 0.f;
        ktab[d * 68 + c] = f2tf_f(kv);
        vtab[d * 72 + c] = f2tf_f(vv);
    }

    // stage Q, K (bf16 gmem -> fp32 smem; bf16 is exact in tf32)
    const __nv_bfloat16* gq = qkv + (size_t)Bidx * TT * (3 * CC) + w * CH;
    #pragma unroll
    for (int it = 0; it < 4; it++) {
        int idx = lane + it * 32;                  // 0..127
        int row = idx >> 3, c8 = (idx & 7) * 8;
        __nv_bfloat162 vq[4], vk[4];
        *(uint4*)vq = *(const uint4*)(gq + (size_t)row * (3 * CC) + c8);
        *(uint4*)vk = *(const uint4*)(gq + (size_t)row * (3 * CC) + CC + c8);
        #pragma unroll
        for (int u = 0; u < 4; u++) {
            float2 fq = __bfloat1622float2(vq[u]);
            float2 fk = __bfloat1622float2(vk[u]);
            bufA[row * 68 + c8 + 2*u]     = fq.x;
            bufA[row * 68 + c8 + 2*u + 1] = fq.y;
            bufB[row * 68 + c8 + 2*u]     = fk.x;
            bufB[row * 68 + c8 + 2*u + 1] = fk.y;
        }
    }
    __syncthreads();

    float c1[2][4] = {{0.f,0.f,0.f,0.f},{0.f,0.f,0.f,0.f}};
    float c2[4][4] = {{0.f,0.f,0.f,0.f},{0.f,0.f,0.f,0.f},{0.f,0.f,0.f,0.f},{0.f,0.f,0.f,0.f}};
    #pragma unroll
    for (int ks = 0; ks < 8; ks++) {
        const int k0 = ks * 8;
        uint32_t a[4];
        a[0] = __float_as_uint(bufA[r * 68 + k0 + qc]);
        a[1] = __float_as_uint(bufA[(r + 8) * 68 + k0 + qc]);
        a[2] = __float_as_uint(bufA[r * 68 + k0 + qc + 4]);
        a[3] = __float_as_uint(bufA[(r + 8) * 68 + k0 + qc + 4]);
        #pragma unroll
        for (int nb = 0; nb < 2; nb++) {
            uint32_t b0 = __float_as_uint(bufB[(nb * 8 + r) * 68 + k0 + qc]);
            uint32_t b1 = __float_as_uint(bufB[(nb * 8 + r) * 68 + k0 + qc + 4]);
            mma_tf32(c1[nb], a, b0, b1);
        }
        #pragma unroll
        for (int nb = 0; nb < 4; nb++) {
            uint32_t b0 = __float_as_uint(ktab[(nb * 8 + r) * 68 + k0 + qc]);
            uint32_t b1 = __float_as_uint(ktab[(nb * 8 + r) * 68 + k0 + qc + 4]);
            mma_tf32(c2[nb], a, b0, b1);
        }
    }
    __syncwarp();

    #pragma unroll
    for (int nb = 0; nb < 4; nb++) {
        #pragma unroll
        for (int q = 0; q < 4; q++) {
            int row = r + (q >> 1) * 8;
            int col = nb * 8 + 2 * qc + (q & 1);
            bufA[row * 33 + col] = c2[nb][q];
        }
    }
    #pragma unroll
    for (int it = 0; it < 28; it++)
        bufB[lane + it * 32] = 0.f;
    __syncwarp();

    float attv[2][4];
    #pragma unroll
    for (int h = 0; h < 2; h++) {
        int row = r + 8 * h;
        float v[4];
        #pragma unroll
        for (int m = 0; m < 4; m++) {
            int nb = m >> 1;
            int j = nb * 8 + 2 * qc + (m & 1);
            v[m] = (c1[nb][h * 2 + (m & 1)] + bufA[row * 33 + (j - row + 15)]) * 0.125f;
        }
        float mx = fmaxf(fmaxf(v[0], v[1]), fmaxf(v[2], v[3]));
        mx = fmaxf(mx, __shfl_xor_sync(0xffffffffu, mx, 1));
        mx = fmaxf(mx, __shfl_xor_sync(0xffffffffu, mx, 2));
        float sum = 0.f;
        #pragma unroll
        for (int m = 0; m < 4; m++) { v[m] = __expf(v[m] - mx); sum += v[m]; }
        sum += __shfl_xor_sync(0xffffffffu, sum, 1);
        sum += __shfl_xor_sync(0xffffffffu, sum, 2);
        float inv = 1.f / sum;
        #pragma unroll
        for (int m = 0; m < 4; m++) attv[h][m] = f2tf_f(v[m] * inv);
    }
    __syncwarp();

    #pragma unroll
    for (int h = 0; h < 2; h++) {
        int row = r + 8 * h;
        #pragma unroll
        for (int m = 0; m < 4; m++) {
            int j = (m >> 1) * 8 + 2 * qc + (m & 1);
            bufB[row * 20 + j] = attv[h][m];
            bufB[320 + row * 36 + (j - row + 15)] = attv[h][m];
        }
    }

    // stage V (bf16 -> fp32 smem)
    #pragma unroll
    for (int it = 0; it < 4; it++) {
        int idx = lane + it * 32;
        int row = idx >> 3, c8 = (idx & 7) * 8;
        __nv_bfloat162 vv[4];
        *(uint4*)vv = *(const uint4*)(gq + (size_t)row * (3 * CC) + 2 * CC + c8);
        #pragma unroll
        for (int u = 0; u < 4; u++) {
            float2 fv = __bfloat1622float2(vv[u]);
            bufA[row * 72 + c8 + 2*u]     = fv.x;
            bufA[row * 72 + c8 + 2*u + 1] = fv.y;
        }
    }
    __syncwarp();

    uint32_t aS[2][4], aS2[4][4];
    #pragma unroll
    for (int ks = 0; ks < 2; ks++) {
        aS[ks][0] = __float_as_uint(bufB[r * 20 + ks * 8 + qc]);
        aS[ks][1] = __float_as_uint(bufB[(r + 8) * 20 + ks * 8 + qc]);
        aS[ks][2] = __float_as_uint(bufB[r * 20 + ks * 8 + qc + 4]);
        aS[ks][3] = __float_as_uint(bufB[(r + 8) * 20 + ks * 8 + qc + 4]);
    }
    #pragma unroll
    for (int ks = 0; ks < 4; ks++) {
        aS2[ks][0] = __float_as_uint(bufB[320 + r * 36 + ks * 8 + qc]);
        aS2[ks][1] = __float_as_uint(bufB[320 + (r + 8) * 36 + ks * 8 + qc]);
        aS2[ks][2] = __float_as_uint(bufB[320 + r * 36 + ks * 8 + qc + 4]);
        aS2[ks][3] = __float_as_uint(bufB[320 + (r + 8) * 36 + ks * 8 + qc + 4]);
    }

    __nv_bfloat16* ga = aout + (size_t)(Bidx * TT) * CC + w * CH;
    #pragma unroll
    for (int nb = 0; nb < 8; nb++) {
        float o[4] = {0.f, 0.f, 0.f, 0.f};
        #pragma unroll
        for (int ks = 0; ks < 2; ks++) {
            uint32_t b0 = __float_as_uint(bufA[(ks * 8 + qc) * 72 + nb * 8 + r]);
            uint32_t b1 = __float_as_uint(bufA[(ks * 8 + qc + 4) * 72 + nb * 8 + r]);
            mma_tf32(o, aS[ks], b0, b1);
        }
        #pragma unroll
        for (int ks = 0; ks < 4; ks++) {
            uint32_t b0 = __float_as_uint(vtab[(ks * 8 + qc) * 72 + nb * 8 + r]);
            uint32_t b1 = __float_as_uint(vtab[(ks * 8 + qc + 4) * 72 + nb * 8 + r]);
            mma_tf32(o, aS2[ks], b0, b1);
        }
        int col = nb * 8 + 2 * qc;
        __nv_bfloat162 p0, p1;
        p0.x = __float2bfloat16_rn(o[0]); p0.y = __float2bfloat16_rn(o[1]);
        p1.x = __float2bfloat16_rn(o[2]); p1.y = __float2bfloat16_rn(o[3]);
        *(__nv_bfloat162*)(ga + (size_t)r * CC + col)       = p0;
        *(__nv_bfloat162*)(ga + (size_t)(r + 8) * CC + col) = p1;
    }
}

// ---------------------------------------------------------------------------
// K5: out = x + transpose-back(proj_seq bf16)
// ---------------------------------------------------------------------------
__global__ __launch_bounds__(256) void k5_resid(const float* __restrict__ x,
                                                const __nv_bfloat16* __restrict__ oseq,
                                                float* __restrict__ out) {
    int bid = blockIdx.x;
    int b = bid >> 9;
    int t = (bid >> 5) & 15;
    int h = bid & 31;
    int tid = threadIdx.x;

    size_t base  = (size_t)b * (CC * TT * HH * WW) + (size_t)t * (HH * WW) + (size_t)h * WW;
    size_t obase = ((size_t)(b * 1024 + h * 32) * TT + t) * CC;

    __shared__ float tile[128 * 33];
    for (int c0 = 0; c0 < CC; c0 += 128) {
        __syncthreads();
        for (int e = tid; e < 128 * 32; e += 256) {
            int ww = e >> 7, cc = e & 127;
            tile[cc * 33 + ww] = __bfloat162float(oseq[obase + (size_t)ww * (TT * CC) + c0 + cc]);
        }
        __syncthreads();
        for (int e = tid; e < 128 * 32; e += 256) {
            int cc = e >> 5, ww = e & 31;
            size_t gi = base + (size_t)(c0 + cc) * (TT*HH*WW) + ww;
            out[gi] = x[gi] + tile[cc * 33 + ww];
        }
    }
}

// ---------------------------------------------------------------------------
extern "C" void kernel_launch(void* const* d_in, const int* in_sizes, int n_in,
                              void* d_out, int out_size) {
    const float* x       = (const float*)d_in[0];
    const float* ln_g    = (const float*)d_in[1];
    const float* ln_b    = (const float*)d_in[2];
    const float* qkv_w   = (const float*)d_in[3];
    const float* qkv_b   = (const float*)d_in[4];
    const float* k_table = (const float*)d_in[5];
    const float* v_table = (const float*)d_in[6];
    const float* proj_w  = (const float*)d_in[7];
    const float* proj_b  = (const float*)d_in[8];
    float* out = (float*)d_out;

    void *p_act_v, *p_qkv_v, *p_attb_v, *p_proj_v, *p_wq_v, *p_wp_v;
    cudaGetSymbolAddress(&p_act_v, g_act);
    cudaGetSymbolAddress(&p_qkv_v, g_qkv);
    cudaGetSymbolAddress(&p_attb_v, g_attb);
    cudaGetSymbolAddress(&p_proj_v, g_proj);
    cudaGetSymbolAddress(&p_wq_v, g_wq);
    cudaGetSymbolAddress(&p_wp_v, g_wp);
    __nv_bfloat16* p_act  = (__nv_bfloat16*)p_act_v;
    __nv_bfloat16* p_qkv  = (__nv_bfloat16*)p_qkv_v;
    __nv_bfloat16* p_attb = (__nv_bfloat16*)p_attb_v;
    __nv_bfloat16* p_proj = (__nv_bfloat16*)p_proj_v;
    __nv_bfloat16* p_wq   = (__nv_bfloat16*)p_wq_v;
    __nv_bfloat16* p_wp   = (__nv_bfloat16*)p_wp_v;

    cudaFuncSetAttribute(tc_gemm, cudaFuncAttributeMaxDynamicSharedMemorySize, GSMEM_SZ);
    cudaFuncSetAttribute(k1_ln, cudaFuncAttributeMaxDynamicSharedMemorySize, K1_SMEM);
    cudaFuncSetAttribute(k3_attn, cudaFuncAttributeMaxDynamicSharedMemorySize, K3_SMEM);

    wcvt<<<(3 * CC * CC + 255) / 256, 256>>>(qkv_w, proj_w, p_wq, p_wp);

    k1_ln<<<BB * TT * HH, 256, K1_SMEM>>>(x, ln_g, ln_b, p_act);

    {
        dim3 grid(3 * CC / 128, ROWS / 128);
        tc_gemm<<<grid, 256, GSMEM_SZ>>>(p_act, p_wq, qkv_b, p_qkv, ROWS, 3 * CC, CC);
    }

    k3_attn<<<BSEQ, 256, K3_SMEM>>>(p_qkv, k_table, v_table, p_attb);

    {
        dim3 grid(CC / 128, ROWS / 128);
        tc_gemm<<<grid, 256, GSMEM_SZ>>>(p_attb, p_wp, proj_b, p_proj, ROWS, CC, CC);
    }

    k5_resid<<<BB * TT * HH, 256>>>(x, p_proj, out);
}

// round 10
// speedup vs baseline: 5.3648x; 1.0021x over previous
#include <cuda_runtime.h>
#include <cuda_bf16.h>
#include <cstdint>

#define BB   2
#define CC   512
#define TT   16
#define HH   32
#define WW   32
#define NH   8
#define CH   64
#define BSEQ (BB*HH*WW)     // 2048
#define ROWS (BSEQ*TT)      // 32768
#define GK   512            // GEMM K (both GEMMs)

__device__ __nv_bfloat16 g_act[(size_t)ROWS * CC];
__device__ __nv_bfloat16 g_qkv[(size_t)ROWS * 3 * CC];
__device__ __nv_bfloat16 g_attb[(size_t)ROWS * CC];
__device__ __nv_bfloat16 g_proj[(size_t)ROWS * CC];
__device__ __nv_bfloat16 g_wq[(size_t)3 * CC * CC];
__device__ __nv_bfloat16 g_wp[(size_t)CC * CC];

// ---------------------------------------------------------------------------
__device__ __forceinline__ uint32_t smem_u32(const void* p) {
    uint32_t a;
    asm("{ .reg .u64 t; cvta.to.shared.u64 t, %1; cvt.u32.u64 %0, t; }" : "=r"(a) : "l"(p));
    return a;
}
#define SWZ(o) ((o) ^ ((((uint32_t)(o)) >> 3) & 0x70))

__device__ __forceinline__ void cpasync16(uint32_t dst, const void* src) {
    asm volatile("cp.async.cg.shared.global [%0], [%1], 16;" :: "r"(dst), "l"(src));
}
__device__ __forceinline__ void ldsm_x4(uint32_t* r, uint32_t addr) {
    asm volatile("ldmatrix.sync.aligned.m8n8.x4.shared.b16 {%0,%1,%2,%3}, [%4];"
                 : "=r"(r[0]), "=r"(r[1]), "=r"(r[2]), "=r"(r[3]) : "r"(addr));
}
__device__ __forceinline__ float f2tf_f(float x) {
    uint32_t y;
    asm("cvt.rna.tf32.f32 %0, %1;" : "=r"(y) : "r"(__float_as_uint(x)));
    return __uint_as_float(y);
}
__device__ __forceinline__ void mma_tf32(float* c, const uint32_t* a, uint32_t b0, uint32_t b1) {
    asm volatile(
        "mma.sync.aligned.m16n8k8.row.col.f32.tf32.tf32.f32 "
        "{%0,%1,%2,%3}, {%4,%5,%6,%7}, {%8,%9}, {%0,%1,%2,%3};"
        : "+f"(c[0]), "+f"(c[1]), "+f"(c[2]), "+f"(c[3])
        : "r"(a[0]), "r"(a[1]), "r"(a[2]), "r"(a[3]), "r"(b0), "r"(b1));
}
__device__ __forceinline__ void mma_bf16(float* c, const uint32_t* a, uint32_t b0, uint32_t b1) {
    asm volatile(
        "mma.sync.aligned.m16n8k16.row.col.f32.bf16.bf16.f32 "
        "{%0,%1,%2,%3}, {%4,%5,%6,%7}, {%8,%9}, {%0,%1,%2,%3};"
        : "+f"(c[0]), "+f"(c[1]), "+f"(c[2]), "+f"(c[3])
        : "r"(a[0]), "r"(a[1]), "r"(a[2]), "r"(a[3]), "r"(b0), "r"(b1));
}

// ---------------------------------------------------------------------------
__global__ __launch_bounds__(256) void wcvt(const float* __restrict__ qkv_w,
                                            const float* __restrict__ proj_w,
                                            __nv_bfloat16* __restrict__ wq,
                                            __nv_bfloat16* __restrict__ wp) {
    int i = blockIdx.x * 256 + threadIdx.x;
    if (i < 3 * CC * CC) wq[i] = __float2bfloat16_rn(qkv_w[i]);
    if (i < CC * CC)     wp[i] = __float2bfloat16_rn(proj_w[i]);
}

// ---------------------------------------------------------------------------
// BF16 tensor GEMM-NT: C[M,N] = A[M,GK] @ W[N,GK]^T + bias, bf16 out
// CTA 128x128, BK=64, 8 warps (64x32 each), 3-stage cp.async, K=512 fixed.
// ---------------------------------------------------------------------------
#define NSTAGE   3
#define STAGE_SZ 32768
#define GSMEM_SZ (NSTAGE*STAGE_SZ)
#define NCH      (GK >> 6)          // 8

__global__ __launch_bounds__(256, 2) void tc_gemm(const __nv_bfloat16* __restrict__ A,
                                                  const __nv_bfloat16* __restrict__ W,
                                                  const float* __restrict__ bias,
                                                  __nv_bfloat16* __restrict__ C,
                                                  int M, int N) {
    extern __shared__ __align__(1024) char smraw[];
    const uint32_t base = smem_u32(smraw);

    const int tid  = threadIdx.x;
    const int wid  = tid >> 5, lane = tid & 31;
    const int wm   = wid & 1, wn = wid >> 1;
    const int bn   = blockIdx.x, bm = blockIdx.y;

    uint32_t st_off[4];
    const __nv_bfloat16* ga[4];
    const __nv_bfloat16* gw[4];
    #pragma unroll
    for (int it = 0; it < 4; it++) {
        int idx = tid + it * 256;
        int r = idx >> 3, c16 = idx & 7;
        st_off[it] = SWZ((uint32_t)(r * 128 + c16 * 16));
        ga[it] = A + (size_t)(bm * 128 + r) * GK + c16 * 8;
        gw[it] = W + (size_t)(bn * 128 + r) * GK + c16 * 8;
    }

    auto load_chunk = [&](int l) {
        const int k0 = l << 6;
        const uint32_t sA = base + (l % NSTAGE) * STAGE_SZ;
        const uint32_t sB = sA + 16384;
        #pragma unroll
        for (int it = 0; it < 4; it++) {
            cpasync16(sA + st_off[it], ga[it] + k0);
            cpasync16(sB + st_off[it], gw[it] + k0);
        }
        asm volatile("cp.async.commit_group;" ::: "memory");
    };

    load_chunk(0);
    load_chunk(1);

    const int m_row_in = ((lane >> 3) & 1) * 8 + (lane & 7);
    const int m_kb     = (lane >> 4) * 16;
    uint32_t a_off[4], b_off[2];
    #pragma unroll
    for (int f = 0; f < 4; f++) {
        int row = wm * 64 + f * 16 + m_row_in;
        a_off[f] = (uint32_t)(row * 128 + (m_kb ^ ((row & 7) << 4)));
    }
    #pragma unroll
    for (int p = 0; p < 2; p++) {
        int row = wn * 32 + p * 16 + m_row_in;
        b_off[p] = (uint32_t)(row * 128 + (m_kb ^ ((row & 7) << 4)));
    }

    float acc[4][4][4];
    #pragma unroll
    for (int f = 0; f < 4; f++)
        #pragma unroll
        for (int g = 0; g < 4; g++)
            #pragma unroll
            for (int r = 0; r < 4; r++) acc[f][g][r] = 0.f;

    #pragma unroll
    for (int c = 0; c < NCH; c++) {
        asm volatile("cp.async.wait_group 1;" ::: "memory");
        __syncthreads();

        if (c + 2 < NCH) load_chunk(c + 2);

        const uint32_t sA = base + (c % NSTAGE) * STAGE_SZ;
        const uint32_t sB = sA + 16384;

        #pragma unroll
        for (int ks = 0; ks < 4; ks++) {
            uint32_t a[4][4], b[2][4];
            #pragma unroll
            for (int f = 0; f < 4; f++)
                ldsm_x4(a[f], sA + (a_off[f] ^ (ks << 5)));
            #pragma unroll
            for (int p = 0; p < 2; p++)
                ldsm_x4(b[p], sB + (b_off[p] ^ (ks << 5)));

            #pragma unroll
            for (int f = 0; f < 4; f++)
                #pragma unroll
                for (int g = 0; g < 4; g++)
                    mma_bf16(acc[f][g], a[f], b[g >> 1][g & 1], b[g >> 1][(g & 1) + 2]);
        }
        __syncthreads();
    }

    const int col_in = 2 * (lane & 3);
    #pragma unroll
    for (int g = 0; g < 4; g++) {
        const int col = bn * 128 + wn * 32 + g * 8 + col_in;
        const float b0 = bias[col], b1 = bias[col + 1];
        #pragma unroll
        for (int f = 0; f < 4; f++) {
            const size_t r0 = (size_t)bm * 128 + wm * 64 + f * 16 + (lane >> 2);
            __nv_bfloat162 p0, p1;
            p0.x = __float2bfloat16_rn(acc[f][g][0] + b0);
            p0.y = __float2bfloat16_rn(acc[f][g][1] + b1);
            p1.x = __float2bfloat16_rn(acc[f][g][2] + b0);
            p1.y = __float2bfloat16_rn(acc[f][g][3] + b1);
            *(__nv_bfloat162*)(C + r0 * N + col)       = p0;
            *(__nv_bfloat162*)(C + (r0 + 8) * N + col) = p1;
        }
    }
}

// ---------------------------------------------------------------------------
// K1: (b,c,t,h,w) -> LayerNorm over c -> bf16 g_act ; vectorized IO
// ---------------------------------------------------------------------------
#define K1_SMEM (512 * 33 * 4)

__global__ __launch_bounds__(256) void k1_ln(const float* __restrict__ x,
                                             const float* __restrict__ gamma,
                                             const float* __restrict__ beta,
                                             __nv_bfloat16* __restrict__ nrm) {
    extern __shared__ float tile[];
    int bid = blockIdx.x;
    int b = bid >> 9;
    int t = (bid >> 5) & 15;
    int h = bid & 31;
    int tid = threadIdx.x;
    int lane = tid & 31, r = tid >> 5;

    size_t xbase = (size_t)b * (CC * TT * HH * WW) + (size_t)t * (HH * WW) + (size_t)h * WW;

    // load: float4 over w (16 iters)
    #pragma unroll
    for (int it = 0; it < 16; it++) {
        int e = tid + it * 256;
        int cc = e >> 3, w4 = (e & 7) * 4;
        float4 v = *(const float4*)(x + xbase + (size_t)cc * (TT*HH*WW) + w4);
        tile[cc * 33 + w4 + 0] = v.x;
        tile[cc * 33 + w4 + 1] = v.y;
        tile[cc * 33 + w4 + 2] = v.z;
        tile[cc * 33 + w4 + 3] = v.w;
    }
    __syncthreads();

    float s = 0.f, s2 = 0.f;
    for (int cc = r; cc < CC; cc += 8) {
        float v = tile[cc * 33 + lane];
        s += v; s2 += v * v;
    }
    __shared__ float red0[8][32], red1[8][32];
    __shared__ float mu_s[32], rs_s[32];
    red0[r][lane] = s; red1[r][lane] = s2;
    __syncthreads();
    if (tid < 32) {
        float a = 0.f, q = 0.f;
        #pragma unroll
        for (int i = 0; i < 8; i++) { a += red0[i][tid]; q += red1[i][tid]; }
        float mu = a * (1.f / CC);
        float var = q * (1.f / CC) - mu * mu;
        mu_s[tid] = mu;
        rs_s[tid] = rsqrtf(var + 1e-5f);
    }
    __syncthreads();

    size_t obase = ((size_t)(b * 1024 + h * 32) * TT + t) * CC;

    // write: bf16x2 over cc (32 iters)
    #pragma unroll
    for (int it = 0; it < 32; it++) {
        int e = tid + it * 256;
        int ww = e >> 8, c2 = (e & 255) * 2;
        float mu = mu_s[ww], rs = rs_s[ww];
        float v0 = (tile[c2 * 33 + ww] - mu) * rs * __ldg(gamma + c2) + __ldg(beta + c2);
        float v1 = (tile[(c2 + 1) * 33 + ww] - mu) * rs * __ldg(gamma + c2 + 1) + __ldg(beta + c2 + 1);
        __nv_bfloat162 p;
        p.x = __float2bfloat16_rn(v0);
        p.y = __float2bfloat16_rn(v1);
        *(__nv_bfloat162*)(nrm + obase + (size_t)ww * (TT * CC) + c2) = p;
    }
}

// ---------------------------------------------------------------------------
// K3: tensor-core attention; V prefetched up front as raw bf16.
// ---------------------------------------------------------------------------
#define K3_SMEM (108032)
#define OFF_KTAB 0
#define OFF_VTAB 2176
#define OFF_BUFA 4480
#define OFF_BUFB (4480 + 8*1152)              // 13696
#define OFF_VRAW (13696 + 8*1088)             // 22400 (floats)

__global__ __launch_bounds__(256, 2) void k3_attn(const __nv_bfloat16* __restrict__ qkv,
                                                  const float* __restrict__ k_table,
                                                  const float* __restrict__ v_table,
                                                  __nv_bfloat16* __restrict__ aout) {
    extern __shared__ float sm[];
    const int tid = threadIdx.x;
    const int w = tid >> 5, lane = tid & 31;
    const int Bidx = blockIdx.x;
    const int r = lane >> 2, qc = lane & 3;

    float* ktab = sm + OFF_KTAB;
    float* vtab = sm + OFF_VTAB;
    float* bufA = sm + OFF_BUFA + w * 1152;
    float* bufB = sm + OFF_BUFB + w * 1088;
    uint4* vraw = (uint4*)(sm + OFF_VRAW) + w * 144;   // 576 floats = 144 uint4 per warp

    #pragma unroll
    for (int it = 0; it < 8; it++) {
        int e = tid + it * 256;
        int d = e >> 6, c = e & 63;
        float kv = (d < 31) ? k_table[(49 + d) * CH + c] : 0.f;
        float vv = (d < 31) ? v_table[(49 + d) * CH + c] : 0.f;
        ktab[d * 68 + c] = f2tf_f(kv);
        vtab[d * 72 + c] = f2tf_f(vv);
    }

    // stage Q, K (bf16 -> fp32 smem) and V (raw bf16 copy) -- all loads upfront
    const __nv_bfloat16* gq = qkv + (size_t)Bidx * TT * (3 * CC) + w * CH;
    #pragma unroll
    for (int it = 0; it < 4; it++) {
        int idx = lane + it * 32;                  // 0..127
        int row = idx >> 3, c8 = (idx & 7) * 8;
        __nv_bfloat162 vq[4], vk[4];
        *(uint4*)vq = *(const uint4*)(gq + (size_t)row * (3 * CC) + c8);
        *(uint4*)vk = *(const uint4*)(gq + (size_t)row * (3 * CC) + CC + c8);
        vraw[row * 9 + (c8 >> 3)] = *(const uint4*)(gq + (size_t)row * (3 * CC) + 2 * CC + c8);
        #pragma unroll
        for (int u = 0; u < 4; u++) {
            float2 fq = __bfloat1622float2(vq[u]);
            float2 fk = __bfloat1622float2(vk[u]);
            bufA[row * 68 + c8 + 2*u]     = fq.x;
            bufA[row * 68 + c8 + 2*u + 1] = fq.y;
            bufB[row * 68 + c8 + 2*u]     = fk.x;
            bufB[row * 68 + c8 + 2*u + 1] = fk.y;
        }
    }
    __syncthreads();

    float c1[2][4] = {{0.f,0.f,0.f,0.f},{0.f,0.f,0.f,0.f}};
    float c2[4][4] = {{0.f,0.f,0.f,0.f},{0.f,0.f,0.f,0.f},{0.f,0.f,0.f,0.f},{0.f,0.f,0.f,0.f}};
    #pragma unroll
    for (int ks = 0; ks < 8; ks++) {
        const int k0 = ks * 8;
        uint32_t a[4];
        a[0] = __float_as_uint(bufA[r * 68 + k0 + qc]);
        a[1] = __float_as_uint(bufA[(r + 8) * 68 + k0 + qc]);
        a[2] = __float_as_uint(bufA[r * 68 + k0 + qc + 4]);
        a[3] = __float_as_uint(bufA[(r + 8) * 68 + k0 + qc + 4]);
        #pragma unroll
        for (int nb = 0; nb < 2; nb++) {
            uint32_t b0 = __float_as_uint(bufB[(nb * 8 + r) * 68 + k0 + qc]);
            uint32_t b1 = __float_as_uint(bufB[(nb * 8 + r) * 68 + k0 + qc + 4]);
            mma_tf32(c1[nb], a, b0, b1);
        }
        #pragma unroll
        for (int nb = 0; nb < 4; nb++) {
            uint32_t b0 = __float_as_uint(ktab[(nb * 8 + r) * 68 + k0 + qc]);
            uint32_t b1 = __float_as_uint(ktab[(nb * 8 + r) * 68 + k0 + qc + 4]);
            mma_tf32(c2[nb], a, b0, b1);
        }
    }
    __syncwarp();

    #pragma unroll
    for (int nb = 0; nb < 4; nb++) {
        #pragma unroll
        for (int q = 0; q < 4; q++) {
            int row = r + (q >> 1) * 8;
            int col = nb * 8 + 2 * qc + (q & 1);
            bufA[row * 33 + col] = c2[nb][q];
        }
    }
    #pragma unroll
    for (int it = 0; it < 28; it++)
        bufB[lane + it * 32] = 0.f;
    __syncwarp();

    float attv[2][4];
    #pragma unroll
    for (int h = 0; h < 2; h++) {
        int row = r + 8 * h;
        float v[4];
        #pragma unroll
        for (int m = 0; m < 4; m++) {
            int nb = m >> 1;
            int j = nb * 8 + 2 * qc + (m & 1);
            v[m] = (c1[nb][h * 2 + (m & 1)] + bufA[row * 33 + (j - row + 15)]) * 0.125f;
        }
        float mx = fmaxf(fmaxf(v[0], v[1]), fmaxf(v[2], v[3]));
        mx = fmaxf(mx, __shfl_xor_sync(0xffffffffu, mx, 1));
        mx = fmaxf(mx, __shfl_xor_sync(0xffffffffu, mx, 2));
        float sum = 0.f;
        #pragma unroll
        for (int m = 0; m < 4; m++) { v[m] = __expf(v[m] - mx); sum += v[m]; }
        sum += __shfl_xor_sync(0xffffffffu, sum, 1);
        sum += __shfl_xor_sync(0xffffffffu, sum, 2);
        float inv = 1.f / sum;
        #pragma unroll
        for (int m = 0; m < 4; m++) attv[h][m] = f2tf_f(v[m] * inv);
    }
    __syncwarp();

    #pragma unroll
    for (int h = 0; h < 2; h++) {
        int row = r + 8 * h;
        #pragma unroll
        for (int m = 0; m < 4; m++) {
            int j = (m >> 1) * 8 + 2 * qc + (m & 1);
            bufB[row * 20 + j] = attv[h][m];
            bufB[320 + row * 36 + (j - row + 15)] = attv[h][m];
        }
    }

    // convert prefetched V: bf16 raw -> fp32 bufA [16][72]
    #pragma unroll
    for (int it = 0; it < 4; it++) {
        int idx = lane + it * 32;
        int row = idx >> 3, c8 = (idx & 7) * 8;
        __nv_bfloat162 vv[4];
        *(uint4*)vv = vraw[row * 9 + (c8 >> 3)];
        float4 lo, hi;
        float2 f0 = __bfloat1622float2(vv[0]);
        float2 f1 = __bfloat1622float2(vv[1]);
        float2 f2 = __bfloat1622float2(vv[2]);
        float2 f3 = __bfloat1622float2(vv[3]);
        lo = make_float4(f0.x, f0.y, f1.x, f1.y);
        hi = make_float4(f2.x, f2.y, f3.x, f3.y);
        *(float4*)(bufA + row * 72 + c8)     = lo;
        *(float4*)(bufA + row * 72 + c8 + 4) = hi;
    }
    __syncwarp();

    uint32_t aS[2][4], aS2[4][4];
    #pragma unroll
    for (int ks = 0; ks < 2; ks++) {
        aS[ks][0] = __float_as_uint(bufB[r * 20 + ks * 8 + qc]);
        aS[ks][1] = __float_as_uint(bufB[(r + 8) * 20 + ks * 8 + qc]);
        aS[ks][2] = __float_as_uint(bufB[r * 20 + ks * 8 + qc + 4]);
        aS[ks][3] = __float_as_uint(bufB[(r + 8) * 20 + ks * 8 + qc + 4]);
    }
    #pragma unroll
    for (int ks = 0; ks < 4; ks++) {
        aS2[ks][0] = __float_as_uint(bufB[320 + r * 36 + ks * 8 + qc]);
        aS2[ks][1] = __float_as_uint(bufB[320 + (r + 8) * 36 + ks * 8 + qc]);
        aS2[ks][2] = __float_as_uint(bufB[320 + r * 36 + ks * 8 + qc + 4]);
        aS2[ks][3] = __float_as_uint(bufB[320 + (r + 8) * 36 + ks * 8 + qc + 4]);
    }

    __nv_bfloat16* ga = aout + (size_t)(Bidx * TT) * CC + w * CH;
    #pragma unroll
    for (int nb = 0; nb < 8; nb++) {
        float o[4] = {0.f, 0.f, 0.f, 0.f};
        #pragma unroll
        for (int ks = 0; ks < 2; ks++) {
            uint32_t b0 = __float_as_uint(bufA[(ks * 8 + qc) * 72 + nb * 8 + r]);
            uint32_t b1 = __float_as_uint(bufA[(ks * 8 + qc + 4) * 72 + nb * 8 + r]);
            mma_tf32(o, aS[ks], b0, b1);
        }
        #pragma unroll
        for (int ks = 0; ks < 4; ks++) {
            uint32_t b0 = __float_as_uint(vtab[(ks * 8 + qc) * 72 + nb * 8 + r]);
            uint32_t b1 = __float_as_uint(vtab[(ks * 8 + qc + 4) * 72 + nb * 8 + r]);
            mma_tf32(o, aS2[ks], b0, b1);
        }
        int col = nb * 8 + 2 * qc;
        __nv_bfloat162 p0, p1;
        p0.x = __float2bfloat16_rn(o[0]); p0.y = __float2bfloat16_rn(o[1]);
        p1.x = __float2bfloat16_rn(o[2]); p1.y = __float2bfloat16_rn(o[3]);
        *(__nv_bfloat162*)(ga + (size_t)r * CC + col)       = p0;
        *(__nv_bfloat162*)(ga + (size_t)(r + 8) * CC + col) = p1;
    }
}

// ---------------------------------------------------------------------------
// K5: out = x + transpose-back(proj_seq bf16)
// ---------------------------------------------------------------------------
__global__ __launch_bounds__(256) void k5_resid(const float* __restrict__ x,
                                                const __nv_bfloat16* __restrict__ oseq,
                                                float* __restrict__ out) {
    int bid = blockIdx.x;
    int b = bid >> 9;
    int t = (bid >> 5) & 15;
    int h = bid & 31;
    int tid = threadIdx.x;

    size_t base  = (size_t)b * (CC * TT * HH * WW) + (size_t)t * (HH * WW) + (size_t)h * WW;
    size_t obase = ((size_t)(b * 1024 + h * 32) * TT + t) * CC;

    __shared__ float tile[128 * 33];
    for (int c0 = 0; c0 < CC; c0 += 128) {
        __syncthreads();
        for (int e = tid; e < 128 * 32; e += 256) {
            int ww = e >> 7, cc = e & 127;
            tile[cc * 33 + ww] = __bfloat162float(oseq[obase + (size_t)ww * (TT * CC) + c0 + cc]);
        }
        __syncthreads();
        for (int e = tid; e < 128 * 32; e += 256) {
            int cc = e >> 5, ww = e & 31;
            size_t gi = base + (size_t)(c0 + cc) * (TT*HH*WW) + ww;
            out[gi] = x[gi] + tile[cc * 33 + ww];
        }
    }
}

// ---------------------------------------------------------------------------
extern "C" void kernel_launch(void* const* d_in, const int* in_sizes, int n_in,
                              void* d_out, int out_size) {
    const float* x       = (const float*)d_in[0];
    const float* ln_g    = (const float*)d_in[1];
    const float* ln_b    = (const float*)d_in[2];
    const float* qkv_w   = (const float*)d_in[3];
    const float* qkv_b   = (const float*)d_in[4];
    const float* k_table = (const float*)d_in[5];
    const float* v_table = (const float*)d_in[6];
    const float* proj_w  = (const float*)d_in[7];
    const float* proj_b  = (const float*)d_in[8];
    float* out = (float*)d_out;

    void *p_act_v, *p_qkv_v, *p_attb_v, *p_proj_v, *p_wq_v, *p_wp_v;
    cudaGetSymbolAddress(&p_act_v, g_act);
    cudaGetSymbolAddress(&p_qkv_v, g_qkv);
    cudaGetSymbolAddress(&p_attb_v, g_attb);
    cudaGetSymbolAddress(&p_proj_v, g_proj);
    cudaGetSymbolAddress(&p_wq_v, g_wq);
    cudaGetSymbolAddress(&p_wp_v, g_wp);
    __nv_bfloat16* p_act  = (__nv_bfloat16*)p_act_v;
    __nv_bfloat16* p_qkv  = (__nv_bfloat16*)p_qkv_v;
    __nv_bfloat16* p_attb = (__nv_bfloat16*)p_attb_v;
    __nv_bfloat16* p_proj = (__nv_bfloat16*)p_proj_v;
    __nv_bfloat16* p_wq   = (__nv_bfloat16*)p_wq_v;
    __nv_bfloat16* p_wp   = (__nv_bfloat16*)p_wp_v;

    cudaFuncSetAttribute(tc_gemm, cudaFuncAttributeMaxDynamicSharedMemorySize, GSMEM_SZ);
    cudaFuncSetAttribute(k1_ln, cudaFuncAttributeMaxDynamicSharedMemorySize, K1_SMEM);
    cudaFuncSetAttribute(k3_attn, cudaFuncAttributeMaxDynamicSharedMemorySize, K3_SMEM);

    wcvt<<<(3 * CC * CC + 255) / 256, 256>>>(qkv_w, proj_w, p_wq, p_wp);

    k1_ln<<<BB * TT * HH, 256, K1_SMEM>>>(x, ln_g, ln_b, p_act);

    {
        dim3 grid(3 * CC / 128, ROWS / 128);
        tc_gemm<<<grid, 256, GSMEM_SZ>>>(p_act, p_wq, qkv_b, p_qkv, ROWS, 3 * CC);
    }

    k3_attn<<<BSEQ, 256, K3_SMEM>>>(p_qkv, k_table, v_table, p_attb);

    {
        dim3 grid(CC / 128, ROWS / 128);
        tc_gemm<<<grid, 256, GSMEM_SZ>>>(p_attb, p_wp, proj_b, p_proj, ROWS, CC);
    }

    k5_resid<<<BB * TT * HH, 256>>>(x, p_proj, out);
}